// round 10
// baseline (speedup 1.0000x reference)
#include <cuda_runtime.h>
#include <cuda_fp16.h>
#include <math_constants.h>
#include <cstdint>

// ---------------- problem constants ----------------
#define BATCH   8
#define EMB     768
#define LSEQ    2304
#define NHEAD   12
#define HDIM    64
#define MROWS   (LSEQ*BATCH)          // 18432
#define NHEADS_TOT (BATCH*NHEAD)      // 96
#define KCH     12                    // K chunks of 64
#define MT      (MROWS/128)           // 144 row-tiles
#define MTG     (MROWS/256)           // 72 GEMM M-tiles
#define NSEG    4
#define LSEG    (LSEQ/NSEG)           // 576
#define GRIDP   148                   // persistent grid

// padded tile: 128 rows x 72 fp16 (144B pitch) = 18432 B
#define TILE_PAD    9216
#define TILE_B      18432
#define SMEM_DATA   221184            // = 4*3*TILE_B = 3*4*TILE_B
#define GEMM_SMEM   (SMEM_DATA + 128)

typedef unsigned long long u64t;

// ---------------- PTX helpers ----------------
__device__ __forceinline__ uint32_t smem_to_u32(const void* p) {
    uint32_t a;
    asm("{ .reg .u64 t; cvta.to.shared.u64 t, %1; cvt.u32.u64 %0, t; }" : "=r"(a) : "l"(p));
    return a;
}
__device__ __forceinline__ void ldsm4(uint32_t& r0, uint32_t& r1, uint32_t& r2, uint32_t& r3,
                                      uint32_t addr) {
    asm volatile("ldmatrix.sync.aligned.m8n8.x4.shared.b16 {%0,%1,%2,%3}, [%4];"
        : "=r"(r0), "=r"(r1), "=r"(r2), "=r"(r3) : "r"(addr));
}
__device__ __forceinline__ void mma16816(float* c, const uint32_t* a, uint32_t b0, uint32_t b1) {
    asm volatile("mma.sync.aligned.m16n8k16.row.col.f32.f16.f16.f32 "
        "{%0,%1,%2,%3}, {%4,%5,%6,%7}, {%8,%9}, {%0,%1,%2,%3};"
        : "+f"(c[0]), "+f"(c[1]), "+f"(c[2]), "+f"(c[3])
        : "r"(a[0]), "r"(a[1]), "r"(a[2]), "r"(a[3]), "r"(b0), "r"(b1));
}
// packed f32x2 (FFMA2 — base sm_100+ PTX)
__device__ __forceinline__ void fma2(u64t& d, u64t a, u64t b) {
    asm("fma.rn.f32x2 %0, %1, %2, %0;" : "+l"(d) : "l"(a), "l"(b));
}
__device__ __forceinline__ u64t packdup(float x) {
    u64t r; asm("mov.b64 %0, {%1, %1};" : "=l"(r) : "f"(x)); return r;
}
__device__ __forceinline__ float2 unpack2(u64t v) {
    float2 r; asm("mov.b64 {%0, %1}, %2;" : "=f"(r.x), "=f"(r.y) : "l"(v)); return r;
}
#define MBARRIER_INIT(addr, cnt) \
    asm volatile("mbarrier.init.shared.b64 [%0], %1;" :: "r"((uint32_t)(addr)), "r"((uint32_t)(cnt)) : "memory")
#define MBARRIER_ARRIVE(addr) \
    asm volatile("mbarrier.arrive.shared.b64 _, [%0];" :: "r"((uint32_t)(addr)) : "memory")
#define MBARRIER_EXPECT_TX(addr, bytes) \
    asm volatile("mbarrier.arrive.expect_tx.shared.b64 _, [%0], %1;" :: "r"((uint32_t)(addr)), "r"((uint32_t)(bytes)) : "memory")
#define MBARRIER_WAIT_PARITY(mbar_smem_addr, phase_parity) do { \
    uint32_t _mbar = (uint32_t)(mbar_smem_addr); \
    uint32_t _parity = (uint32_t)(phase_parity); \
    uint32_t _done; \
    asm volatile("{\n\t.reg .pred p;\n\t" \
        "mbarrier.try_wait.parity.acquire.cta.shared::cta.b64 p, [%1], %2;\n\t" \
        "selp.b32 %0, 1, 0, p;\n\t}" \
        : "=r"(_done) : "r"(_mbar), "r"(_parity) : "memory"); \
    if (!_done) { \
        asm volatile("{\n\t.reg .pred P1;\n\t" \
            "WAIT_LOOP_%=:\n\t" \
            "mbarrier.try_wait.parity.acquire.cta.shared::cta.b64 P1, [%0], %1, 0x989680;\n\t" \
            "@P1 bra.uni WAIT_DONE_%=;\n\t" \
            "bra.uni WAIT_LOOP_%=;\n\t" \
            "WAIT_DONE_%=:\n\t}" \
            :: "r"(_mbar), "r"(_parity) : "memory"); \
    } \
} while(0)
__device__ __forceinline__ void bulk_g2s(uint32_t dst_smem, const void* gsrc, uint32_t bytes, uint32_t mbar) {
    asm volatile(
        "cp.async.bulk.shared::cluster.global.mbarrier::complete_tx::bytes [%0], [%1], %2, [%3];"
        :: "r"(dst_smem), "l"(gsrc), "r"(bytes), "r"(mbar) : "memory");
}

// ---------------- scratch globals ----------------
__device__ __align__(1024) float d_X[MROWS*EMB];
__device__ __align__(1024) __half d_Qh[MROWS*EMB];
__device__ __align__(1024) __half d_Kh[MROWS*EMB];
__device__ __align__(1024) __half d_Vh[MROWS*EMB];
__device__ __align__(1024) __half d_Xh[MT*KCH*TILE_PAD];
__device__ __align__(1024) __half d_Yh[MT*KCH*TILE_PAD];
__device__ __align__(1024) __half d_Wqkv[18*KCH*TILE_PAD];
__device__ __align__(1024) __half d_Wo_hi[6*KCH*TILE_PAD];
__device__ __align__(1024) __half d_Wo_lo[6*KCH*TILE_PAD];
__device__ float d_kv[NSEG*NHEADS_TOT*128*64];
__device__ float d_ksum[NSEG*NHEADS_TOT*128];
__device__ float d_sinb[LSEQ];
__device__ float d_cosb[LSEQ];

__device__ __forceinline__ uint32_t tiled_idx(int tile, int r, int k) {
    return (uint32_t)tile * TILE_PAD + (uint32_t)r * 72u + (uint32_t)k;
}

// ---------------- sin/cos table ----------------
__global__ void sincos_kernel() {
    int l = blockIdx.x * blockDim.x + threadIdx.x;
    if (l < LSEQ) {
        float ang = (0.5f * CUDART_PI_F) * (float)(l + 1) / (float)LSEQ;
        d_sinb[l] = sinf(ang);
        d_cosb[l] = cosf(ang);
    }
}

// ---------------- weight conversions ----------------
__global__ void wconv3_kernel(const float* __restrict__ Wq, const float* __restrict__ Wk,
                              const float* __restrict__ Wv) {
    int which = blockIdx.y;
    const float* W = (which == 0) ? Wq : (which == 1) ? Wk : Wv;
    int nt_base = which * 6;
    int idx = blockIdx.x * 256 + threadIdx.x;
    if (idx >= EMB * EMB) return;
    int n = idx / EMB, e = idx % EMB;
    uint32_t t = tiled_idx((nt_base + (n >> 7)) * KCH + (e >> 6), n & 127, e & 63);
    d_Wqkv[t] = __float2half(W[idx]);
}

__global__ void wconvO_kernel(const float* __restrict__ W) {
    int idx = blockIdx.x * 256 + threadIdx.x;
    if (idx >= EMB * EMB) return;
    int n = idx / EMB, e = idx % EMB;
    float x = W[idx];
    __half h = __float2half(x);
    __half l = __float2half(x - __half2float(h));
    uint32_t t = tiled_idx(((n >> 7)) * KCH + (e >> 6), n & 127, e & 63);
    d_Wo_hi[t] = h; d_Wo_lo[t] = l;
}

// ---------------- transpose (B,E,L)->(L*B,E): fp32 X + plain fp16 tiles -----
__global__ void transpose_kernel(const float* __restrict__ q) {
    __shared__ float tile[32][33];
    int b  = blockIdx.z;
    int l0 = blockIdx.x * 32;
    int e0 = blockIdx.y * 32;
    int tx = threadIdx.x, ty = threadIdx.y;   // 32 x 8
    const float* src = q + (size_t)b * EMB * LSEQ;
    #pragma unroll
    for (int i = 0; i < 32; i += 8)
        tile[ty + i][tx] = src[(size_t)(e0 + ty + i) * LSEQ + l0 + tx];
    __syncthreads();
    #pragma unroll
    for (int i = 0; i < 32; i += 8) {
        int l = l0 + ty + i;
        int e = e0 + tx;
        int m = l * BATCH + b;
        float v = tile[tx][ty + i];
        d_X[(size_t)m * EMB + e] = v;
        uint32_t t = tiled_idx((m >> 7) * KCH + (e >> 6), m & 127, e & 63);
        d_Xh[t] = __float2half(v);
    }
}

// ---------------- persistent HMMA GEMM 256x128 ----------------
// PROD=1: A plain, B plain, fp16 out -> 3 tiles/stage, 4 stages (QKV)
// PROD=2: A plain, B hi/lo, fp32 out -> 4 tiles/stage, 3 stages (O-proj)
// Persistent: grid=148, each CTA loops over tiles bid, bid+148, ... with a
// continuous cross-tile pipeline (prologue once; next tile prefetched during
// current tile's epilogue).
template <int PROD>
__global__ __launch_bounds__(256, 1) void tcgemm_kernel(
    const __half* __restrict__ A,
    const __half* __restrict__ Bhi, const __half* __restrict__ Blo,
    const float* __restrict__ b0p, const float* __restrict__ b1p, const float* __restrict__ b2p,
    void* __restrict__ C0, void* __restrict__ C1, void* __restrict__ C2,
    int reluMask, int nTilesTotal)
{
    constexpr int NST  = (PROD == 1) ? 4 : 3;
    constexpr int NTIL = (PROD == 1) ? 3 : 4;
    constexpr uint32_t STAGE_BYTES = NTIL * TILE_B;

    extern __shared__ __align__(1024) char smem[];
    uint32_t sb = smem_to_u32(smem);
    int tid  = threadIdx.x;
    int lane = tid & 31, wid = tid >> 5;
    int bid  = blockIdx.x;
    int wm = wid & 3;      // M offset wm*64
    int wn = wid >> 2;     // N offset wn*64

    int nLocal = (nTilesTotal - bid + GRIDP - 1) / GRIDP;
    if (nLocal <= 0) return;
    int totC = nLocal * KCH;

    uint32_t mb_full  = sb + SMEM_DATA;
    uint32_t mb_empty = sb + SMEM_DATA + 48;

    if (tid == 0) {
        #pragma unroll
        for (int s = 0; s < NST; s++) {
            MBARRIER_INIT(mb_full + 8 * s, 1);
            MBARRIER_INIT(mb_empty + 8 * s, 256);
        }
        asm volatile("fence.proxy.async.shared::cta;" ::: "memory");
    }
    __syncthreads();

    int emptyPh[NST], fullPh[NST];
    #pragma unroll
    for (int s = 0; s < NST; s++) { emptyPh[s] = 1; fullPh[s] = 0; }

    // produce global-chunk gc (gc = localTile*KCH + c)
    auto produce = [&](int gc) {
        if (tid == 0 && gc < totC) {
            int j = gc / KCH, c = gc - j * KCH;
            int tile = bid + j * GRIDP;
            int mt = tile % MTG, nt = tile / MTG;
            const __half* gA   = A + (size_t)(2 * mt) * KCH * TILE_PAD;
            const __half* gBhi = Bhi + (size_t)nt * KCH * TILE_PAD;
            int s = gc % NST;
            MBARRIER_WAIT_PARITY(mb_empty + 8 * s, emptyPh[s]);
            emptyPh[s] ^= 1;
            uint32_t dst = sb + s * STAGE_BYTES;
            uint32_t mbar = mb_full + 8 * s;
            MBARRIER_EXPECT_TX(mbar, STAGE_BYTES);
            bulk_g2s(dst,          gA + (size_t)c * TILE_PAD,         TILE_B, mbar);
            bulk_g2s(dst + TILE_B, gA + (size_t)(KCH + c) * TILE_PAD, TILE_B, mbar);
            bulk_g2s(dst + 2 * TILE_B, gBhi + (size_t)c * TILE_PAD, TILE_B, mbar);
            if (PROD == 2) {
                const __half* gBlo = Blo + (size_t)nt * KCH * TILE_PAD;
                bulk_g2s(dst + 3 * TILE_B, gBlo + (size_t)c * TILE_PAD, TILE_B, mbar);
            }
        }
    };

    int a_mr = lane & 15;
    int a_ks = lane >> 4;
    int b_nr = ((lane >> 4) << 3) | (lane & 7);
    int b_ks = (lane >> 3) & 1;

    #pragma unroll
    for (int s = 0; s < NST; s++) produce(s);

    int gc = 0;
    for (int j = 0; j < nLocal; j++) {
        int tile = bid + j * GRIDP;
        int mt = tile % MTG, nt = tile / MTG;
        int sel = nt / 6, ntc = nt % 6;
        const float* bias = (sel == 0) ? b0p : (sel == 1) ? b1p : b2p;
        void* C = (sel == 0) ? C0 : (sel == 1) ? C1 : C2;
        int doRelu = (reluMask >> sel) & 1;

        float acc[4][8][4];
        #pragma unroll
        for (int t = 0; t < 4; t++)
            #pragma unroll
            for (int jj = 0; jj < 8; jj++)
                #pragma unroll
                for (int i = 0; i < 4; i++) acc[t][jj][i] = 0.f;

        for (int c = 0; c < KCH; c++, gc++) {
            int s = gc % NST;
            MBARRIER_WAIT_PARITY(mb_full + 8 * s, fullPh[s]);
            fullPh[s] ^= 1;

            uint32_t stB = sb + s * STAGE_BYTES;
            uint32_t A_b   = stB + (wm >> 1) * TILE_B;
            uint32_t Bhi_b = stB + 2 * TILE_B;
            uint32_t Blo_b = stB + 3 * TILE_B;
            uint32_t aRow0 = (uint32_t)((wm & 1) * 64);

            #pragma unroll
            for (int ks = 0; ks < 4; ks++) {
                uint32_t ah[4][4], bb[4][4];
                #pragma unroll
                for (int t = 0; t < 4; t++) {
                    uint32_t off = (aRow0 + t * 16 + a_mr) * 144u + ks * 32u + a_ks * 16u;
                    ldsm4(ah[t][0], ah[t][1], ah[t][2], ah[t][3], A_b + off);
                }
                #pragma unroll
                for (int g = 0; g < 4; g++) {
                    uint32_t off = (uint32_t)(wn * 64 + g * 16 + b_nr) * 144u + ks * 32u + b_ks * 16u;
                    ldsm4(bb[g][0], bb[g][1], bb[g][2], bb[g][3], Bhi_b + off);
                }
                #pragma unroll
                for (int t = 0; t < 4; t++)
                    #pragma unroll
                    for (int jj = 0; jj < 8; jj++)
                        mma16816(acc[t][jj], ah[t], bb[jj >> 1][2 * (jj & 1)], bb[jj >> 1][2 * (jj & 1) + 1]);
                if (PROD == 2) {
                    #pragma unroll
                    for (int g = 0; g < 4; g++) {
                        uint32_t off = (uint32_t)(wn * 64 + g * 16 + b_nr) * 144u + ks * 32u + b_ks * 16u;
                        ldsm4(bb[g][0], bb[g][1], bb[g][2], bb[g][3], Blo_b + off);
                    }
                    #pragma unroll
                    for (int t = 0; t < 4; t++)
                        #pragma unroll
                        for (int jj = 0; jj < 8; jj++)
                            mma16816(acc[t][jj], ah[t], bb[jj >> 1][2 * (jj & 1)], bb[jj >> 1][2 * (jj & 1) + 1]);
                }
            }
            MBARRIER_ARRIVE(mb_empty + 8 * s);
            produce(gc + NST);
        }

        // epilogue (next tile's chunks already streaming in)
        int g = lane >> 2, tq = lane & 3;
        int mbase = mt * 256 + (wm >> 1) * 128 + (wm & 1) * 64;
        #pragma unroll
        for (int t = 0; t < 4; t++) {
            int r0 = mbase + t * 16 + g;
            #pragma unroll
            for (int jj = 0; jj < 8; jj++) {
                int col = ntc * 128 + wn * 64 + jj * 8 + tq * 2;
                float b0 = __ldg(&bias[col]), b1 = __ldg(&bias[col + 1]);
                float v0 = acc[t][jj][0] + b0, v1 = acc[t][jj][1] + b1;
                float v2 = acc[t][jj][2] + b0, v3 = acc[t][jj][3] + b1;
                if (doRelu) {
                    v0 = fmaxf(v0, 0.f); v1 = fmaxf(v1, 0.f);
                    v2 = fmaxf(v2, 0.f); v3 = fmaxf(v3, 0.f);
                }
                if (PROD == 1) {
                    __half* Ch = (__half*)C;
                    *(__half2*)&Ch[(size_t)r0 * EMB + col]       = __floats2half2_rn(v0, v1);
                    *(__half2*)&Ch[(size_t)(r0 + 8) * EMB + col] = __floats2half2_rn(v2, v3);
                } else {
                    float* Cf = (float*)C;
                    *(float2*)&Cf[(size_t)r0 * EMB + col]       = make_float2(v0, v1);
                    *(float2*)&Cf[(size_t)(r0 + 8) * EMB + col] = make_float2(v2, v3);
                }
            }
        }
    }
}

// ---------------- attention stage 1 (fp16 inputs, packed f32x2) -------------
#define CH 8
__global__ __launch_bounds__(256) void attn_kv_kernel() {
    __shared__ float sk[CH][128];
    __shared__ float sv[CH][64];
    int n   = blockIdx.x;
    int seg = blockIdx.y;
    int b = n / NHEAD, hh = n % NHEAD;
    int tid = threadIdx.x;
    int dkg = tid & 31;
    int dvg = tid >> 5;

    u64t acc2[4][4];
    #pragma unroll
    for (int i = 0; i < 4; i++)
        #pragma unroll
        for (int j = 0; j < 4; j++) acc2[i][j] = 0ull;
    float ks[4] = {0.f, 0.f, 0.f, 0.f};

    int lbeg = seg * LSEG, lend = lbeg + LSEG;
    for (int l0 = lbeg; l0 < lend; l0 += CH) {
        __syncthreads();
        #pragma unroll
        for (int i = 0; i < 2; i++) {
            int idx = tid + i * 256;
            int lc = idx >> 6, t = idx & 63;
            int l = l0 + lc;
            size_t base = ((size_t)l * BATCH + b) * EMB + hh * HDIM + t;
            float kval = __half2float(d_Kh[base]);
            float s = d_sinb[l], c = d_cosb[l];
            sk[lc][t]      = kval * s;
            sk[lc][t + 64] = kval * c;
            sv[lc][t]      = __half2float(d_Vh[base]);
        }
        __syncthreads();
        #pragma unroll
        for (int lc = 0; lc < CH; lc++) {
            float4 kk4 = *(const float4*)&sk[lc][dkg * 4];
            float4 v0  = *(const float4*)&sv[lc][dvg * 8];
            float4 v1  = *(const float4*)&sv[lc][dvg * 8 + 4];
            u64t vv2[4];
            vv2[0] = ((const u64t*)&v0)[0]; vv2[1] = ((const u64t*)&v0)[1];
            vv2[2] = ((const u64t*)&v1)[0]; vv2[3] = ((const u64t*)&v1)[1];
            float kka[4] = {kk4.x, kk4.y, kk4.z, kk4.w};
            ks[0] += kka[0]; ks[1] += kka[1]; ks[2] += kka[2]; ks[3] += kka[3];
            #pragma unroll
            for (int i = 0; i < 4; i++) {
                u64t kp = packdup(kka[i]);
                #pragma unroll
                for (int j = 0; j < 4; j++)
                    fma2(acc2[i][j], kp, vv2[j]);
            }
        }
    }

    float* kvp = d_kv + ((size_t)seg * NHEADS_TOT + n) * 8192;
    #pragma unroll
    for (int i = 0; i < 4; i++)
        #pragma unroll
        for (int j = 0; j < 4; j++) {
            float2 p = unpack2(acc2[i][j]);
            *(float2*)&kvp[(dkg * 4 + i) * 64 + dvg * 8 + 2 * j] = p;
        }
    if (dvg == 0) {
        #pragma unroll
        for (int i = 0; i < 4; i++)
            d_ksum[(seg * NHEADS_TOT + n) * 128 + dkg * 4 + i] = ks[i];
    }
}

// ---------------- attention stage 2 (fp16 Q, folded sin/cos, f32x2) ---------
__global__ __launch_bounds__(256) void attn_out_kernel() {
    __shared__ float skv[128 * 64];
    __shared__ float sks[128];
    int n   = blockIdx.x;
    int seg = blockIdx.y;
    int b = n / NHEAD, hh = n % NHEAD;
    int tid = threadIdx.x;
    int warp = tid >> 5, lane = tid & 31;

    for (int idx = tid; idx < 8192; idx += 256) {
        float v = 0.f;
        #pragma unroll
        for (int s = 0; s < NSEG; s++)
            v += d_kv[((size_t)s * NHEADS_TOT + n) * 8192 + idx];
        skv[idx] = v;
    }
    if (tid < 128) {
        float v = 0.f;
        #pragma unroll
        for (int s = 0; s < NSEG; s++)
            v += d_ksum[(s * NHEADS_TOT + n) * 128 + tid];
        sks[tid] = v;
    }
    __syncthreads();

    const u64t* skv2 = (const u64t*)skv;   // [dk][dv-pair]: idx = dk*32 + pair

    int lbeg = seg * LSEG;
    for (int l = lbeg + warp; l < lbeg + LSEG; l += 8) {
        size_t base = ((size_t)l * BATCH + b) * EMB + hh * HDIM;
        float q0 = __half2float(d_Qh[base + lane]);
        float q1 = __half2float(d_Qh[base + 32 + lane]);
        float s = d_sinb[l], c = d_cosb[l];

        float dps = q0 * sks[lane] + q1 * sks[lane + 32];
        float dpc = q0 * sks[lane + 64] + q1 * sks[lane + 96];
        #pragma unroll
        for (int o = 16; o; o >>= 1) {
            dps += __shfl_xor_sync(0xffffffffu, dps, o);
            dpc += __shfl_xor_sync(0xffffffffu, dpc, o);
        }
        float z = 1.0f / fmaxf(s * dps + c * dpc, 1e-6f);

        u64t os2 = 0ull, oc2 = 0ull;
        #pragma unroll
        for (int t = 0; t < 32; t++) {
            float qb = __shfl_sync(0xffffffffu, q0, t);
            u64t qp = packdup(qb);
            fma2(os2, qp, skv2[t * 32 + lane]);
            fma2(oc2, qp, skv2[(64 + t) * 32 + lane]);
        }
        #pragma unroll
        for (int t = 0; t < 32; t++) {
            float qb = __shfl_sync(0xffffffffu, q1, t);
            u64t qp = packdup(qb);
            fma2(os2, qp, skv2[(32 + t) * 32 + lane]);
            fma2(oc2, qp, skv2[(96 + t) * 32 + lane]);
        }

        u64t o2 = 0ull;
        fma2(o2, os2, packdup(s));
        fma2(o2, oc2, packdup(c));

        float2 xv = *(const float2*)&d_X[base + 2 * lane];
        u64t r2 = ((const u64t*)&xv)[0];
        fma2(r2, o2, packdup(z));
        float2 y = unpack2(r2);

        int m = l * BATCH + b;
        int tile = (m >> 7) * KCH + hh;
        uint32_t ti = tiled_idx(tile, m & 127, 2 * lane);
        *(__half2*)&d_Yh[ti] = __floats2half2_rn(y.x, y.y);
    }
}

// ---------------- launch ----------------
extern "C" void kernel_launch(void* const* d_in, const int* in_sizes, int n_in,
                              void* d_out, int out_size) {
    const float* query = (const float*)d_in[0];
    const float* Wq = (const float*)d_in[1];
    const float* bq = (const float*)d_in[2];
    const float* Wk = (const float*)d_in[3];
    const float* bk = (const float*)d_in[4];
    const float* Wv = (const float*)d_in[5];
    const float* bv = (const float*)d_in[6];
    const float* Wo = (const float*)d_in[7];
    const float* bo = (const float*)d_in[8];
    float* out = (float*)d_out;

    __half *pQh, *pKh, *pVh, *pXh, *pYh, *pWqkv, *pWoHi, *pWoLo;
    cudaGetSymbolAddress((void**)&pQh, d_Qh);
    cudaGetSymbolAddress((void**)&pKh, d_Kh);
    cudaGetSymbolAddress((void**)&pVh, d_Vh);
    cudaGetSymbolAddress((void**)&pXh, d_Xh);
    cudaGetSymbolAddress((void**)&pYh, d_Yh);
    cudaGetSymbolAddress((void**)&pWqkv, d_Wqkv);
    cudaGetSymbolAddress((void**)&pWoHi, d_Wo_hi);
    cudaGetSymbolAddress((void**)&pWoLo, d_Wo_lo);

    cudaFuncSetAttribute(tcgemm_kernel<1>, cudaFuncAttributeMaxDynamicSharedMemorySize, GEMM_SMEM);
    cudaFuncSetAttribute(tcgemm_kernel<2>, cudaFuncAttributeMaxDynamicSharedMemorySize, GEMM_SMEM);

    // order: capture slot (4th launch) = combined QKV GEMM
    dim3 tgrid(LSEQ / 32, EMB / 32, BATCH);
    transpose_kernel<<<tgrid, dim3(32, 8)>>>(query);                     // 1
    const int wgrid = (EMB * EMB + 255) / 256;
    wconv3_kernel<<<dim3(wgrid, 3), 256>>>(Wq, Wk, Wv);                  // 2
    wconvO_kernel<<<wgrid, 256>>>(Wo);                                   // 3

    // 4: combined QKV GEMM — persistent, 18*72 = 1296 tiles
    tcgemm_kernel<1><<<GRIDP, 256, GEMM_SMEM>>>(
        pXh, pWqkv, nullptr, bq, bk, bv, pQh, pKh, pVh, 0b011, 18 * MTG);

    sincos_kernel<<<(LSEQ + 255) / 256, 256>>>();                        // 5
    attn_kv_kernel<<<dim3(NHEADS_TOT, NSEG), 256>>>();                   // 6
    attn_out_kernel<<<dim3(NHEADS_TOT, NSEG), 256>>>();                  // 7

    // 8: O projection — persistent, 6*72 = 432 tiles
    tcgemm_kernel<2><<<GRIDP, 256, GEMM_SMEM>>>(
        pYh, pWoHi, pWoLo, bo, bo, bo, out, out, out, 0, 6 * MTG);
}

// round 11
// speedup vs baseline: 1.0347x; 1.0347x over previous
#include <cuda_runtime.h>
#include <cuda_fp16.h>
#include <math_constants.h>
#include <cstdint>

// ---------------- problem constants ----------------
#define BATCH   8
#define EMB     768
#define LSEQ    2304
#define NHEAD   12
#define HDIM    64
#define MROWS   (LSEQ*BATCH)          // 18432
#define NHEADS_TOT (BATCH*NHEAD)      // 96
#define KCH     12                    // K chunks of 64
#define MT      (MROWS/128)           // 144 row-tiles (= GEMM M-tiles now)
#define NSEG    4
#define LSEG    (LSEQ/NSEG)           // 576

// padded tile: 128 rows x 72 fp16 (144B pitch) = 18432 B
#define TILE_PAD    9216
#define TILE_B      18432
#define SMEM_DATA   110592            // = 3*2*TILE_B = 2*3*TILE_B (per CTA)
#define GEMM_SMEM   (SMEM_DATA + 128)

typedef unsigned long long u64t;

// ---------------- PTX helpers ----------------
__device__ __forceinline__ uint32_t smem_to_u32(const void* p) {
    uint32_t a;
    asm("{ .reg .u64 t; cvta.to.shared.u64 t, %1; cvt.u32.u64 %0, t; }" : "=r"(a) : "l"(p));
    return a;
}
__device__ __forceinline__ void ldsm4(uint32_t& r0, uint32_t& r1, uint32_t& r2, uint32_t& r3,
                                      uint32_t addr) {
    asm volatile("ldmatrix.sync.aligned.m8n8.x4.shared.b16 {%0,%1,%2,%3}, [%4];"
        : "=r"(r0), "=r"(r1), "=r"(r2), "=r"(r3) : "r"(addr));
}
__device__ __forceinline__ void mma16816(float* c, const uint32_t* a, uint32_t b0, uint32_t b1) {
    asm volatile("mma.sync.aligned.m16n8k16.row.col.f32.f16.f16.f32 "
        "{%0,%1,%2,%3}, {%4,%5,%6,%7}, {%8,%9}, {%0,%1,%2,%3};"
        : "+f"(c[0]), "+f"(c[1]), "+f"(c[2]), "+f"(c[3])
        : "r"(a[0]), "r"(a[1]), "r"(a[2]), "r"(a[3]), "r"(b0), "r"(b1));
}
// packed f32x2 (FFMA2 — base sm_100+ PTX)
__device__ __forceinline__ void fma2(u64t& d, u64t a, u64t b) {
    asm("fma.rn.f32x2 %0, %1, %2, %0;" : "+l"(d) : "l"(a), "l"(b));
}
__device__ __forceinline__ u64t packdup(float x) {
    u64t r; asm("mov.b64 %0, {%1, %1};" : "=l"(r) : "f"(x)); return r;
}
__device__ __forceinline__ float2 unpack2(u64t v) {
    float2 r; asm("mov.b64 {%0, %1}, %2;" : "=f"(r.x), "=f"(r.y) : "l"(v)); return r;
}
#define MBARRIER_INIT(addr, cnt) \
    asm volatile("mbarrier.init.shared.b64 [%0], %1;" :: "r"((uint32_t)(addr)), "r"((uint32_t)(cnt)) : "memory")
#define MBARRIER_ARRIVE(addr) \
    asm volatile("mbarrier.arrive.shared.b64 _, [%0];" :: "r"((uint32_t)(addr)) : "memory")
#define MBARRIER_EXPECT_TX(addr, bytes) \
    asm volatile("mbarrier.arrive.expect_tx.shared.b64 _, [%0], %1;" :: "r"((uint32_t)(addr)), "r"((uint32_t)(bytes)) : "memory")
#define MBARRIER_WAIT_PARITY(mbar_smem_addr, phase_parity) do { \
    uint32_t _mbar = (uint32_t)(mbar_smem_addr); \
    uint32_t _parity = (uint32_t)(phase_parity); \
    uint32_t _done; \
    asm volatile("{\n\t.reg .pred p;\n\t" \
        "mbarrier.try_wait.parity.acquire.cta.shared::cta.b64 p, [%1], %2;\n\t" \
        "selp.b32 %0, 1, 0, p;\n\t}" \
        : "=r"(_done) : "r"(_mbar), "r"(_parity) : "memory"); \
    if (!_done) { \
        asm volatile("{\n\t.reg .pred P1;\n\t" \
            "WAIT_LOOP_%=:\n\t" \
            "mbarrier.try_wait.parity.acquire.cta.shared::cta.b64 P1, [%0], %1, 0x989680;\n\t" \
            "@P1 bra.uni WAIT_DONE_%=;\n\t" \
            "bra.uni WAIT_LOOP_%=;\n\t" \
            "WAIT_DONE_%=:\n\t}" \
            :: "r"(_mbar), "r"(_parity) : "memory"); \
    } \
} while(0)
__device__ __forceinline__ void bulk_g2s(uint32_t dst_smem, const void* gsrc, uint32_t bytes, uint32_t mbar) {
    asm volatile(
        "cp.async.bulk.shared::cluster.global.mbarrier::complete_tx::bytes [%0], [%1], %2, [%3];"
        :: "r"(dst_smem), "l"(gsrc), "r"(bytes), "r"(mbar) : "memory");
}

// ---------------- scratch globals ----------------
__device__ __align__(1024) float d_X[MROWS*EMB];
__device__ __align__(1024) __half d_Qh[MROWS*EMB];
__device__ __align__(1024) __half d_Kh[MROWS*EMB];
__device__ __align__(1024) __half d_Vh[MROWS*EMB];
__device__ __align__(1024) __half d_Xh[MT*KCH*TILE_PAD];
__device__ __align__(1024) __half d_Yh[MT*KCH*TILE_PAD];
__device__ __align__(1024) __half d_Wqkv[18*KCH*TILE_PAD];
__device__ __align__(1024) __half d_Wo_hi[6*KCH*TILE_PAD];
__device__ __align__(1024) __half d_Wo_lo[6*KCH*TILE_PAD];
__device__ float d_kv[NSEG*NHEADS_TOT*128*64];
__device__ float d_ksum[NSEG*NHEADS_TOT*128];
__device__ float d_sinb[LSEQ];
__device__ float d_cosb[LSEQ];

__device__ __forceinline__ uint32_t tiled_idx(int tile, int r, int k) {
    return (uint32_t)tile * TILE_PAD + (uint32_t)r * 72u + (uint32_t)k;
}

// ---------------- sin/cos table ----------------
__global__ void sincos_kernel() {
    int l = blockIdx.x * blockDim.x + threadIdx.x;
    if (l < LSEQ) {
        float ang = (0.5f * CUDART_PI_F) * (float)(l + 1) / (float)LSEQ;
        d_sinb[l] = sinf(ang);
        d_cosb[l] = cosf(ang);
    }
}

// ---------------- weight conversions ----------------
__global__ void wconv3_kernel(const float* __restrict__ Wq, const float* __restrict__ Wk,
                              const float* __restrict__ Wv) {
    int which = blockIdx.y;
    const float* W = (which == 0) ? Wq : (which == 1) ? Wk : Wv;
    int nt_base = which * 6;
    int idx = blockIdx.x * 256 + threadIdx.x;
    if (idx >= EMB * EMB) return;
    int n = idx / EMB, e = idx % EMB;
    uint32_t t = tiled_idx((nt_base + (n >> 7)) * KCH + (e >> 6), n & 127, e & 63);
    d_Wqkv[t] = __float2half(W[idx]);
}

__global__ void wconvO_kernel(const float* __restrict__ W) {
    int idx = blockIdx.x * 256 + threadIdx.x;
    if (idx >= EMB * EMB) return;
    int n = idx / EMB, e = idx % EMB;
    float x = W[idx];
    __half h = __float2half(x);
    __half l = __float2half(x - __half2float(h));
    uint32_t t = tiled_idx(((n >> 7)) * KCH + (e >> 6), n & 127, e & 63);
    d_Wo_hi[t] = h; d_Wo_lo[t] = l;
}

// ---------------- transpose (B,E,L)->(L*B,E): fp32 X + plain fp16 tiles -----
__global__ void transpose_kernel(const float* __restrict__ q) {
    __shared__ float tile[32][33];
    int b  = blockIdx.z;
    int l0 = blockIdx.x * 32;
    int e0 = blockIdx.y * 32;
    int tx = threadIdx.x, ty = threadIdx.y;   // 32 x 8
    const float* src = q + (size_t)b * EMB * LSEQ;
    #pragma unroll
    for (int i = 0; i < 32; i += 8)
        tile[ty + i][tx] = src[(size_t)(e0 + ty + i) * LSEQ + l0 + tx];
    __syncthreads();
    #pragma unroll
    for (int i = 0; i < 32; i += 8) {
        int l = l0 + ty + i;
        int e = e0 + tx;
        int m = l * BATCH + b;
        float v = tile[tx][ty + i];
        d_X[(size_t)m * EMB + e] = v;
        uint32_t t = tiled_idx((m >> 7) * KCH + (e >> 6), m & 127, e & 63);
        d_Xh[t] = __float2half(v);
    }
}

// ---------------- HMMA GEMM 128x128 tile, 128 threads, 2 CTAs/SM ------------
// PROD=1: A plain, B plain, fp16 out -> 2 tiles/stage, 3 stages (QKV)
// PROD=2: A plain, B hi/lo, fp32 out -> 3 tiles/stage, 2 stages (O-proj)
// Two co-resident CTAs per SM cover each other's barrier/epilogue bubbles.
template <int PROD>
__global__ __launch_bounds__(128, 2) void tcgemm_kernel(
    const __half* __restrict__ A,
    const __half* __restrict__ Bhi, const __half* __restrict__ Blo,
    const float* __restrict__ b0p, const float* __restrict__ b1p, const float* __restrict__ b2p,
    void* __restrict__ C0, void* __restrict__ C1, void* __restrict__ C2,
    int reluMask)
{
    constexpr int NST  = (PROD == 1) ? 3 : 2;
    constexpr int NTIL = (PROD == 1) ? 2 : 3;
    constexpr uint32_t STAGE_BYTES = NTIL * TILE_B;

    extern __shared__ __align__(1024) char smem[];
    uint32_t sb = smem_to_u32(smem);
    int tid  = threadIdx.x;
    int lane = tid & 31, wid = tid >> 5;   // 4 warps
    int nt = blockIdx.x, mt = blockIdx.y;
    int sel = nt / 6, ntc = nt % 6;
    const float* bias = (sel == 0) ? b0p : (sel == 1) ? b1p : b2p;
    void* C = (sel == 0) ? C0 : (sel == 1) ? C1 : C2;
    int doRelu = (reluMask >> sel) & 1;
    int wm = wid & 1;      // M offset wm*64
    int wn = wid >> 1;     // N offset wn*64

    uint32_t mb_full  = sb + SMEM_DATA;
    uint32_t mb_empty = sb + SMEM_DATA + 48;

    if (tid == 0) {
        #pragma unroll
        for (int s = 0; s < NST; s++) {
            MBARRIER_INIT(mb_full + 8 * s, 1);
            MBARRIER_INIT(mb_empty + 8 * s, 128);
        }
        asm volatile("fence.proxy.async.shared::cta;" ::: "memory");
    }
    __syncthreads();

    const __half* gA   = A + (size_t)mt * KCH * TILE_PAD;
    const __half* gBhi = Bhi + (size_t)nt * KCH * TILE_PAD;
    const __half* gBlo = (PROD == 2) ? (Blo + (size_t)nt * KCH * TILE_PAD) : nullptr;

    int emptyPh[NST], fullPh[NST];
    #pragma unroll
    for (int s = 0; s < NST; s++) { emptyPh[s] = 1; fullPh[s] = 0; }

    auto produce = [&](int c) {
        if (tid == 0) {
            int s = c % NST;
            MBARRIER_WAIT_PARITY(mb_empty + 8 * s, emptyPh[s]);
            emptyPh[s] ^= 1;
            uint32_t dst = sb + s * STAGE_BYTES;
            uint32_t mbar = mb_full + 8 * s;
            MBARRIER_EXPECT_TX(mbar, STAGE_BYTES);
            bulk_g2s(dst,          gA + (size_t)c * TILE_PAD,   TILE_B, mbar);
            bulk_g2s(dst + TILE_B, gBhi + (size_t)c * TILE_PAD, TILE_B, mbar);
            if (PROD == 2)
                bulk_g2s(dst + 2 * TILE_B, gBlo + (size_t)c * TILE_PAD, TILE_B, mbar);
        }
    };

    float acc[4][8][4];
    #pragma unroll
    for (int t = 0; t < 4; t++)
        #pragma unroll
        for (int j = 0; j < 8; j++)
            #pragma unroll
            for (int i = 0; i < 4; i++) acc[t][j][i] = 0.f;

    int a_mr = lane & 15;
    int a_ks = lane >> 4;
    int b_nr = ((lane >> 4) << 3) | (lane & 7);
    int b_ks = (lane >> 3) & 1;

    #pragma unroll
    for (int s = 0; s < NST; s++) produce(s);

    for (int c = 0; c < KCH; c++) {
        int s = c % NST;
        MBARRIER_WAIT_PARITY(mb_full + 8 * s, fullPh[s]);
        fullPh[s] ^= 1;

        uint32_t stB = sb + s * STAGE_BYTES;
        uint32_t A_b   = stB;
        uint32_t Bhi_b = stB + TILE_B;
        uint32_t Blo_b = stB + 2 * TILE_B;
        uint32_t aRow0 = (uint32_t)(wm * 64);

        #pragma unroll
        for (int ks = 0; ks < 4; ks++) {
            uint32_t ah[4][4], bb[4][4];
            #pragma unroll
            for (int t = 0; t < 4; t++) {
                uint32_t off = (aRow0 + t * 16 + a_mr) * 144u + ks * 32u + a_ks * 16u;
                ldsm4(ah[t][0], ah[t][1], ah[t][2], ah[t][3], A_b + off);
            }
            #pragma unroll
            for (int g = 0; g < 4; g++) {
                uint32_t off = (uint32_t)(wn * 64 + g * 16 + b_nr) * 144u + ks * 32u + b_ks * 16u;
                ldsm4(bb[g][0], bb[g][1], bb[g][2], bb[g][3], Bhi_b + off);
            }
            #pragma unroll
            for (int t = 0; t < 4; t++)
                #pragma unroll
                for (int j = 0; j < 8; j++)
                    mma16816(acc[t][j], ah[t], bb[j >> 1][2 * (j & 1)], bb[j >> 1][2 * (j & 1) + 1]);
            if (PROD == 2) {
                #pragma unroll
                for (int g = 0; g < 4; g++) {
                    uint32_t off = (uint32_t)(wn * 64 + g * 16 + b_nr) * 144u + ks * 32u + b_ks * 16u;
                    ldsm4(bb[g][0], bb[g][1], bb[g][2], bb[g][3], Blo_b + off);
                }
                #pragma unroll
                for (int t = 0; t < 4; t++)
                    #pragma unroll
                    for (int j = 0; j < 8; j++)
                        mma16816(acc[t][j], ah[t], bb[j >> 1][2 * (j & 1)], bb[j >> 1][2 * (j & 1) + 1]);
            }
        }
        MBARRIER_ARRIVE(mb_empty + 8 * s);
        if (c + NST < KCH) produce(c + NST);
    }

    // epilogue
    int g = lane >> 2, tq = lane & 3;
    int mbase = mt * 128 + wm * 64;
    #pragma unroll
    for (int t = 0; t < 4; t++) {
        int r0 = mbase + t * 16 + g;
        #pragma unroll
        for (int j = 0; j < 8; j++) {
            int col = ntc * 128 + wn * 64 + j * 8 + tq * 2;
            float b0 = __ldg(&bias[col]), b1 = __ldg(&bias[col + 1]);
            float v0 = acc[t][j][0] + b0, v1 = acc[t][j][1] + b1;
            float v2 = acc[t][j][2] + b0, v3 = acc[t][j][3] + b1;
            if (doRelu) {
                v0 = fmaxf(v0, 0.f); v1 = fmaxf(v1, 0.f);
                v2 = fmaxf(v2, 0.f); v3 = fmaxf(v3, 0.f);
            }
            if (PROD == 1) {
                __half* Ch = (__half*)C;
                *(__half2*)&Ch[(size_t)r0 * EMB + col]       = __floats2half2_rn(v0, v1);
                *(__half2*)&Ch[(size_t)(r0 + 8) * EMB + col] = __floats2half2_rn(v2, v3);
            } else {
                float* Cf = (float*)C;
                *(float2*)&Cf[(size_t)r0 * EMB + col]       = make_float2(v0, v1);
                *(float2*)&Cf[(size_t)(r0 + 8) * EMB + col] = make_float2(v2, v3);
            }
        }
    }
}

// ---------------- attention stage 1 (fp16 inputs, packed f32x2) -------------
#define CH 8
__global__ __launch_bounds__(256) void attn_kv_kernel() {
    __shared__ float sk[CH][128];
    __shared__ float sv[CH][64];
    int n   = blockIdx.x;
    int seg = blockIdx.y;
    int b = n / NHEAD, hh = n % NHEAD;
    int tid = threadIdx.x;
    int dkg = tid & 31;
    int dvg = tid >> 5;

    u64t acc2[4][4];
    #pragma unroll
    for (int i = 0; i < 4; i++)
        #pragma unroll
        for (int j = 0; j < 4; j++) acc2[i][j] = 0ull;
    float ks[4] = {0.f, 0.f, 0.f, 0.f};

    int lbeg = seg * LSEG, lend = lbeg + LSEG;
    for (int l0 = lbeg; l0 < lend; l0 += CH) {
        __syncthreads();
        #pragma unroll
        for (int i = 0; i < 2; i++) {
            int idx = tid + i * 256;
            int lc = idx >> 6, t = idx & 63;
            int l = l0 + lc;
            size_t base = ((size_t)l * BATCH + b) * EMB + hh * HDIM + t;
            float kval = __half2float(d_Kh[base]);
            float s = d_sinb[l], c = d_cosb[l];
            sk[lc][t]      = kval * s;
            sk[lc][t + 64] = kval * c;
            sv[lc][t]      = __half2float(d_Vh[base]);
        }
        __syncthreads();
        #pragma unroll
        for (int lc = 0; lc < CH; lc++) {
            float4 kk4 = *(const float4*)&sk[lc][dkg * 4];
            float4 v0  = *(const float4*)&sv[lc][dvg * 8];
            float4 v1  = *(const float4*)&sv[lc][dvg * 8 + 4];
            u64t vv2[4];
            vv2[0] = ((const u64t*)&v0)[0]; vv2[1] = ((const u64t*)&v0)[1];
            vv2[2] = ((const u64t*)&v1)[0]; vv2[3] = ((const u64t*)&v1)[1];
            float kka[4] = {kk4.x, kk4.y, kk4.z, kk4.w};
            ks[0] += kka[0]; ks[1] += kka[1]; ks[2] += kka[2]; ks[3] += kka[3];
            #pragma unroll
            for (int i = 0; i < 4; i++) {
                u64t kp = packdup(kka[i]);
                #pragma unroll
                for (int j = 0; j < 4; j++)
                    fma2(acc2[i][j], kp, vv2[j]);
            }
        }
    }

    float* kvp = d_kv + ((size_t)seg * NHEADS_TOT + n) * 8192;
    #pragma unroll
    for (int i = 0; i < 4; i++)
        #pragma unroll
        for (int j = 0; j < 4; j++) {
            float2 p = unpack2(acc2[i][j]);
            *(float2*)&kvp[(dkg * 4 + i) * 64 + dvg * 8 + 2 * j] = p;
        }
    if (dvg == 0) {
        #pragma unroll
        for (int i = 0; i < 4; i++)
            d_ksum[(seg * NHEADS_TOT + n) * 128 + dkg * 4 + i] = ks[i];
    }
}

// ---------------- attention stage 2 (fp16 Q, folded sin/cos, f32x2) ---------
__global__ __launch_bounds__(256) void attn_out_kernel() {
    __shared__ float skv[128 * 64];
    __shared__ float sks[128];
    int n   = blockIdx.x;
    int seg = blockIdx.y;
    int b = n / NHEAD, hh = n % NHEAD;
    int tid = threadIdx.x;
    int warp = tid >> 5, lane = tid & 31;

    for (int idx = tid; idx < 8192; idx += 256) {
        float v = 0.f;
        #pragma unroll
        for (int s = 0; s < NSEG; s++)
            v += d_kv[((size_t)s * NHEADS_TOT + n) * 8192 + idx];
        skv[idx] = v;
    }
    if (tid < 128) {
        float v = 0.f;
        #pragma unroll
        for (int s = 0; s < NSEG; s++)
            v += d_ksum[(s * NHEADS_TOT + n) * 128 + tid];
        sks[tid] = v;
    }
    __syncthreads();

    const u64t* skv2 = (const u64t*)skv;   // [dk][dv-pair]: idx = dk*32 + pair

    int lbeg = seg * LSEG;
    for (int l = lbeg + warp; l < lbeg + LSEG; l += 8) {
        size_t base = ((size_t)l * BATCH + b) * EMB + hh * HDIM;
        float q0 = __half2float(d_Qh[base + lane]);
        float q1 = __half2float(d_Qh[base + 32 + lane]);
        float s = d_sinb[l], c = d_cosb[l];

        float dps = q0 * sks[lane] + q1 * sks[lane + 32];
        float dpc = q0 * sks[lane + 64] + q1 * sks[lane + 96];
        #pragma unroll
        for (int o = 16; o; o >>= 1) {
            dps += __shfl_xor_sync(0xffffffffu, dps, o);
            dpc += __shfl_xor_sync(0xffffffffu, dpc, o);
        }
        float z = 1.0f / fmaxf(s * dps + c * dpc, 1e-6f);

        u64t os2 = 0ull, oc2 = 0ull;
        #pragma unroll
        for (int t = 0; t < 32; t++) {
            float qb = __shfl_sync(0xffffffffu, q0, t);
            u64t qp = packdup(qb);
            fma2(os2, qp, skv2[t * 32 + lane]);
            fma2(oc2, qp, skv2[(64 + t) * 32 + lane]);
        }
        #pragma unroll
        for (int t = 0; t < 32; t++) {
            float qb = __shfl_sync(0xffffffffu, q1, t);
            u64t qp = packdup(qb);
            fma2(os2, qp, skv2[(32 + t) * 32 + lane]);
            fma2(oc2, qp, skv2[(96 + t) * 32 + lane]);
        }

        u64t o2 = 0ull;
        fma2(o2, os2, packdup(s));
        fma2(o2, oc2, packdup(c));

        float2 xv = *(const float2*)&d_X[base + 2 * lane];
        u64t r2 = ((const u64t*)&xv)[0];
        fma2(r2, o2, packdup(z));
        float2 y = unpack2(r2);

        int m = l * BATCH + b;
        int tile = (m >> 7) * KCH + hh;
        uint32_t ti = tiled_idx(tile, m & 127, 2 * lane);
        *(__half2*)&d_Yh[ti] = __floats2half2_rn(y.x, y.y);
    }
}

// ---------------- launch ----------------
extern "C" void kernel_launch(void* const* d_in, const int* in_sizes, int n_in,
                              void* d_out, int out_size) {
    const float* query = (const float*)d_in[0];
    const float* Wq = (const float*)d_in[1];
    const float* bq = (const float*)d_in[2];
    const float* Wk = (const float*)d_in[3];
    const float* bk = (const float*)d_in[4];
    const float* Wv = (const float*)d_in[5];
    const float* bv = (const float*)d_in[6];
    const float* Wo = (const float*)d_in[7];
    const float* bo = (const float*)d_in[8];
    float* out = (float*)d_out;

    __half *pQh, *pKh, *pVh, *pXh, *pYh, *pWqkv, *pWoHi, *pWoLo;
    cudaGetSymbolAddress((void**)&pQh, d_Qh);
    cudaGetSymbolAddress((void**)&pKh, d_Kh);
    cudaGetSymbolAddress((void**)&pVh, d_Vh);
    cudaGetSymbolAddress((void**)&pXh, d_Xh);
    cudaGetSymbolAddress((void**)&pYh, d_Yh);
    cudaGetSymbolAddress((void**)&pWqkv, d_Wqkv);
    cudaGetSymbolAddress((void**)&pWoHi, d_Wo_hi);
    cudaGetSymbolAddress((void**)&pWoLo, d_Wo_lo);

    cudaFuncSetAttribute(tcgemm_kernel<1>, cudaFuncAttributeMaxDynamicSharedMemorySize, GEMM_SMEM);
    cudaFuncSetAttribute(tcgemm_kernel<2>, cudaFuncAttributeMaxDynamicSharedMemorySize, GEMM_SMEM);

    // order: capture slot (4th launch) = combined QKV GEMM
    dim3 tgrid(LSEQ / 32, EMB / 32, BATCH);
    transpose_kernel<<<tgrid, dim3(32, 8)>>>(query);                     // 1
    const int wgrid = (EMB * EMB + 255) / 256;
    wconv3_kernel<<<dim3(wgrid, 3), 256>>>(Wq, Wk, Wv);                  // 2
    wconvO_kernel<<<wgrid, 256>>>(Wo);                                   // 3

    // 4: combined QKV GEMM — 128x128 tiles, 2 CTAs/SM (18 x 144 grid)
    tcgemm_kernel<1><<<dim3(18, MT), 128, GEMM_SMEM>>>(
        pXh, pWqkv, nullptr, bq, bk, bv, pQh, pKh, pVh, 0b011);

    sincos_kernel<<<(LSEQ + 255) / 256, 256>>>();                        // 5
    attn_kv_kernel<<<dim3(NHEADS_TOT, NSEG), 256>>>();                   // 6
    attn_out_kernel<<<dim3(NHEADS_TOT, NSEG), 256>>>();                  // 7

    // 8: O projection — 128x128 tiles, 2 CTAs/SM (6 x 144 grid)
    tcgemm_kernel<2><<<dim3(6, MT), 128, GEMM_SMEM>>>(
        pYh, pWoHi, pWoLo, bo, bo, bo, out, out, out, 0);
}

// round 12
// speedup vs baseline: 1.9397x; 1.8747x over previous
#include <cuda_runtime.h>
#include <cuda_fp16.h>
#include <math_constants.h>
#include <cstdint>

// ---------------- problem constants ----------------
#define BATCH   8
#define EMB     768
#define LSEQ    2304
#define NHEAD   12
#define HDIM    64
#define MROWS   (LSEQ*BATCH)          // 18432
#define NHEADS_TOT (BATCH*NHEAD)      // 96
#define KCH     12                    // K chunks of 64
#define MT      (MROWS/128)           // 144 GEMM M-tiles
#define NSEG    4
#define LSEG    (LSEQ/NSEG)           // 576

// padded tile: 128 rows x 72 fp16 (144B pitch) = 18432 B
#define TILE_PAD    9216
#define TILE_B      18432
#define SMEM_DATA   110592            // 3 stages x 2 tiles
#define GEMM_SMEM   (SMEM_DATA + 128)

typedef unsigned long long u64t;

// ---------------- PTX helpers ----------------
__device__ __forceinline__ uint32_t smem_to_u32(const void* p) {
    uint32_t a;
    asm("{ .reg .u64 t; cvta.to.shared.u64 t, %1; cvt.u32.u64 %0, t; }" : "=r"(a) : "l"(p));
    return a;
}
__device__ __forceinline__ void ldsm4(uint32_t* r, uint32_t addr) {
    asm volatile("ldmatrix.sync.aligned.m8n8.x4.shared.b16 {%0,%1,%2,%3}, [%4];"
        : "=r"(r[0]), "=r"(r[1]), "=r"(r[2]), "=r"(r[3]) : "r"(addr));
}
__device__ __forceinline__ void ldsm4t(uint32_t* r, uint32_t addr) {
    asm volatile("ldmatrix.sync.aligned.m8n8.x4.trans.shared.b16 {%0,%1,%2,%3}, [%4];"
        : "=r"(r[0]), "=r"(r[1]), "=r"(r[2]), "=r"(r[3]) : "r"(addr));
}
__device__ __forceinline__ void mma16816(float* c, const uint32_t* a, uint32_t b0, uint32_t b1) {
    asm volatile("mma.sync.aligned.m16n8k16.row.col.f32.f16.f16.f32 "
        "{%0,%1,%2,%3}, {%4,%5,%6,%7}, {%8,%9}, {%0,%1,%2,%3};"
        : "+f"(c[0]), "+f"(c[1]), "+f"(c[2]), "+f"(c[3])
        : "r"(a[0]), "r"(a[1]), "r"(a[2]), "r"(a[3]), "r"(b0), "r"(b1));
}
#define MBARRIER_INIT(addr, cnt) \
    asm volatile("mbarrier.init.shared.b64 [%0], %1;" :: "r"((uint32_t)(addr)), "r"((uint32_t)(cnt)) : "memory")
#define MBARRIER_ARRIVE(addr) \
    asm volatile("mbarrier.arrive.shared.b64 _, [%0];" :: "r"((uint32_t)(addr)) : "memory")
#define MBARRIER_EXPECT_TX(addr, bytes) \
    asm volatile("mbarrier.arrive.expect_tx.shared.b64 _, [%0], %1;" :: "r"((uint32_t)(addr)), "r"((uint32_t)(bytes)) : "memory")
#define MBARRIER_WAIT_PARITY(mbar_smem_addr, phase_parity) do { \
    uint32_t _mbar = (uint32_t)(mbar_smem_addr); \
    uint32_t _parity = (uint32_t)(phase_parity); \
    uint32_t _done; \
    asm volatile("{\n\t.reg .pred p;\n\t" \
        "mbarrier.try_wait.parity.acquire.cta.shared::cta.b64 p, [%1], %2;\n\t" \
        "selp.b32 %0, 1, 0, p;\n\t}" \
        : "=r"(_done) : "r"(_mbar), "r"(_parity) : "memory"); \
    if (!_done) { \
        asm volatile("{\n\t.reg .pred P1;\n\t" \
            "WAIT_LOOP_%=:\n\t" \
            "mbarrier.try_wait.parity.acquire.cta.shared::cta.b64 P1, [%0], %1, 0x989680;\n\t" \
            "@P1 bra.uni WAIT_DONE_%=;\n\t" \
            "bra.uni WAIT_LOOP_%=;\n\t" \
            "WAIT_DONE_%=:\n\t}" \
            :: "r"(_mbar), "r"(_parity) : "memory"); \
    } \
} while(0)
__device__ __forceinline__ void bulk_g2s(uint32_t dst_smem, const void* gsrc, uint32_t bytes, uint32_t mbar) {
    asm volatile(
        "cp.async.bulk.shared::cluster.global.mbarrier::complete_tx::bytes [%0], [%1], %2, [%3];"
        :: "r"(dst_smem), "l"(gsrc), "r"(bytes), "r"(mbar) : "memory");
}

// ---------------- scratch globals ----------------
__device__ __align__(1024) float d_X[MROWS*EMB];
__device__ __align__(1024) __half d_Qh[MROWS*EMB];
__device__ __align__(1024) __half d_Kh[MROWS*EMB];
__device__ __align__(1024) __half d_Vh[MROWS*EMB];
__device__ __align__(1024) __half d_Xh[MT*KCH*TILE_PAD];
__device__ __align__(1024) __half d_Yh[MT*KCH*TILE_PAD];
__device__ __align__(1024) __half d_Wqkv[18*KCH*TILE_PAD];
__device__ __align__(1024) __half d_Wo[6*KCH*TILE_PAD];
__device__ float d_kvT[NSEG*NHEADS_TOT*64*128];   // [seg][head][dv][dk] fp32 partials
__device__ float d_ksum[NSEG*NHEADS_TOT*128];

__device__ __forceinline__ uint32_t tiled_idx(int tile, int r, int k) {
    return (uint32_t)tile * TILE_PAD + (uint32_t)r * 72u + (uint32_t)k;
}

// ---------------- weight conversions ----------------
__global__ void wconv3_kernel(const float* __restrict__ Wq, const float* __restrict__ Wk,
                              const float* __restrict__ Wv) {
    int which = blockIdx.y;
    const float* W = (which == 0) ? Wq : (which == 1) ? Wk : Wv;
    int nt_base = which * 6;
    int idx = blockIdx.x * 256 + threadIdx.x;
    if (idx >= EMB * EMB) return;
    int n = idx / EMB, e = idx % EMB;
    uint32_t t = tiled_idx((nt_base + (n >> 7)) * KCH + (e >> 6), n & 127, e & 63);
    d_Wqkv[t] = __float2half(W[idx]);
}

__global__ void wconvO_kernel(const float* __restrict__ W) {
    int idx = blockIdx.x * 256 + threadIdx.x;
    if (idx >= EMB * EMB) return;
    int n = idx / EMB, e = idx % EMB;
    uint32_t t = tiled_idx(((n >> 7)) * KCH + (e >> 6), n & 127, e & 63);
    d_Wo[t] = __float2half(W[idx]);
}

// ---------------- transpose (B,E,L)->(L*B,E): fp32 X + plain fp16 tiles -----
__global__ void transpose_kernel(const float* __restrict__ q) {
    __shared__ float tile[32][33];
    int b  = blockIdx.z;
    int l0 = blockIdx.x * 32;
    int e0 = blockIdx.y * 32;
    int tx = threadIdx.x, ty = threadIdx.y;   // 32 x 8
    const float* src = q + (size_t)b * EMB * LSEQ;
    #pragma unroll
    for (int i = 0; i < 32; i += 8)
        tile[ty + i][tx] = src[(size_t)(e0 + ty + i) * LSEQ + l0 + tx];
    __syncthreads();
    #pragma unroll
    for (int i = 0; i < 32; i += 8) {
        int l = l0 + ty + i;
        int e = e0 + tx;
        int m = l * BATCH + b;
        float v = tile[tx][ty + i];
        d_X[(size_t)m * EMB + e] = v;
        uint32_t t = tiled_idx((m >> 7) * KCH + (e >> 6), m & 127, e & 63);
        d_Xh[t] = __float2half(v);
    }
}

// ---------------- HMMA GEMM 128x128 tile, 128 threads, single product -------
// OUT32=0: fp16 output (QKV).  OUT32=1: fp32 output (O-projection).
template <int OUT32>
__global__ __launch_bounds__(128, 2) void tcgemm_kernel(
    const __half* __restrict__ A, const __half* __restrict__ B,
    const float* __restrict__ b0p, const float* __restrict__ b1p, const float* __restrict__ b2p,
    void* __restrict__ C0, void* __restrict__ C1, void* __restrict__ C2,
    int reluMask)
{
    constexpr int NST = 3;
    constexpr uint32_t STAGE_BYTES = 2 * TILE_B;

    extern __shared__ __align__(1024) char smem[];
    uint32_t sb = smem_to_u32(smem);
    int tid  = threadIdx.x;
    int lane = tid & 31, wid = tid >> 5;   // 4 warps
    int nt = blockIdx.x, mt = blockIdx.y;
    int sel = nt / 6, ntc = nt % 6;
    const float* bias = (sel == 0) ? b0p : (sel == 1) ? b1p : b2p;
    void* C = (sel == 0) ? C0 : (sel == 1) ? C1 : C2;
    int doRelu = (reluMask >> sel) & 1;
    int wm = wid & 1;      // M offset wm*64
    int wn = wid >> 1;     // N offset wn*64

    uint32_t mb_full  = sb + SMEM_DATA;
    uint32_t mb_empty = sb + SMEM_DATA + 48;

    if (tid == 0) {
        #pragma unroll
        for (int s = 0; s < NST; s++) {
            MBARRIER_INIT(mb_full + 8 * s, 1);
            MBARRIER_INIT(mb_empty + 8 * s, 128);
        }
        asm volatile("fence.proxy.async.shared::cta;" ::: "memory");
    }
    __syncthreads();

    const __half* gA = A + (size_t)mt * KCH * TILE_PAD;
    const __half* gB = B + (size_t)nt * KCH * TILE_PAD;

    int emptyPh[NST], fullPh[NST];
    #pragma unroll
    for (int s = 0; s < NST; s++) { emptyPh[s] = 1; fullPh[s] = 0; }

    auto produce = [&](int c) {
        if (tid == 0) {
            int s = c % NST;
            MBARRIER_WAIT_PARITY(mb_empty + 8 * s, emptyPh[s]);
            emptyPh[s] ^= 1;
            uint32_t dst = sb + s * STAGE_BYTES;
            uint32_t mbar = mb_full + 8 * s;
            MBARRIER_EXPECT_TX(mbar, STAGE_BYTES);
            bulk_g2s(dst,          gA + (size_t)c * TILE_PAD, TILE_B, mbar);
            bulk_g2s(dst + TILE_B, gB + (size_t)c * TILE_PAD, TILE_B, mbar);
        }
    };

    float acc[4][8][4];
    #pragma unroll
    for (int t = 0; t < 4; t++)
        #pragma unroll
        for (int j = 0; j < 8; j++)
            #pragma unroll
            for (int i = 0; i < 4; i++) acc[t][j][i] = 0.f;

    int a_mr = lane & 15;
    int a_ks = lane >> 4;
    int b_nr = ((lane >> 4) << 3) | (lane & 7);
    int b_ks = (lane >> 3) & 1;

    #pragma unroll
    for (int s = 0; s < NST; s++) produce(s);

    for (int c = 0; c < KCH; c++) {
        int s = c % NST;
        MBARRIER_WAIT_PARITY(mb_full + 8 * s, fullPh[s]);
        fullPh[s] ^= 1;

        uint32_t stB = sb + s * STAGE_BYTES;
        uint32_t aRow0 = (uint32_t)(wm * 64);

        #pragma unroll
        for (int ks = 0; ks < 4; ks++) {
            uint32_t ah[4][4], bb[4][4];
            #pragma unroll
            for (int t = 0; t < 4; t++) {
                uint32_t off = (aRow0 + t * 16 + a_mr) * 144u + ks * 32u + a_ks * 16u;
                ldsm4(ah[t], stB + off);
            }
            #pragma unroll
            for (int g = 0; g < 4; g++) {
                uint32_t off = (uint32_t)(wn * 64 + g * 16 + b_nr) * 144u + ks * 32u + b_ks * 16u;
                ldsm4(bb[g], stB + TILE_B + off);
            }
            #pragma unroll
            for (int t = 0; t < 4; t++)
                #pragma unroll
                for (int j = 0; j < 8; j++)
                    mma16816(acc[t][j], ah[t], bb[j >> 1][2 * (j & 1)], bb[j >> 1][2 * (j & 1) + 1]);
        }
        MBARRIER_ARRIVE(mb_empty + 8 * s);
        if (c + NST < KCH) produce(c + NST);
    }

    // epilogue
    int g = lane >> 2, tq = lane & 3;
    int mbase = mt * 128 + wm * 64;
    #pragma unroll
    for (int t = 0; t < 4; t++) {
        int r0 = mbase + t * 16 + g;
        #pragma unroll
        for (int j = 0; j < 8; j++) {
            int col = ntc * 128 + wn * 64 + j * 8 + tq * 2;
            float b0 = __ldg(&bias[col]), b1 = __ldg(&bias[col + 1]);
            float v0 = acc[t][j][0] + b0, v1 = acc[t][j][1] + b1;
            float v2 = acc[t][j][2] + b0, v3 = acc[t][j][3] + b1;
            if (doRelu) {
                v0 = fmaxf(v0, 0.f); v1 = fmaxf(v1, 0.f);
                v2 = fmaxf(v2, 0.f); v3 = fmaxf(v3, 0.f);
            }
            if (!OUT32) {
                __half* Ch = (__half*)C;
                *(__half2*)&Ch[(size_t)r0 * EMB + col]       = __floats2half2_rn(v0, v1);
                *(__half2*)&Ch[(size_t)(r0 + 8) * EMB + col] = __floats2half2_rn(v2, v3);
            } else {
                float* Cf = (float*)C;
                *(float2*)&Cf[(size_t)r0 * EMB + col]       = make_float2(v0, v1);
                *(float2*)&Cf[(size_t)(r0 + 8) * EMB + col] = make_float2(v2, v3);
            }
        }
    }
}

// ---------------- attention stage 1: HMMA kv reduction ----------------------
// Block (head n, seg): kvT_part[64dv][128dk] = sum_l v[l]^T outer k_[l],
// via D[128dk, 64dv] mma with A = k_^T (ldmatrix.trans), B = v^T (trans).
#define KV_LST 64
__global__ __launch_bounds__(128) void attn_kv_kernel() {
    __shared__ __half sk[KV_LST][136];   // k_ = [k*sin | k*cos], 272B pitch
    __shared__ __half sv[KV_LST][72];    // v, 144B pitch
    __shared__ float ssin[KV_LST], scos[KV_LST];
    int n = blockIdx.x, seg = blockIdx.y;
    int b = n / NHEAD, hh = n % NHEAD;
    int tid = threadIdx.x, lane = tid & 31, wid = tid >> 5;
    uint32_t skb = smem_to_u32(sk), svb = smem_to_u32(sv);

    float acc[2][8][4];
    #pragma unroll
    for (int t = 0; t < 2; t++)
        #pragma unroll
        for (int j = 0; j < 8; j++)
            #pragma unroll
            for (int i = 0; i < 4; i++) acc[t][j][i] = 0.f;
    float ksum = 0.f;   // per-thread: dk = tid

    // trans-ldmatrix lane address components
    int a_sr = (lane & 7) + ((lane >> 4) << 3);        // A: l-row within 16
    int a_sc = ((lane >> 3) & 1) * 8;                  // A: dk offset within 16
    int b_sr = (lane & 7) + (((lane >> 3) & 1) << 3);  // B: l-row within 16
    int b_sc = (lane >> 4) * 8;                        // B: dv offset within 16

    int lbeg = seg * LSEG;
    for (int ls = 0; ls < LSEG; ls += KV_LST) {
        __syncthreads();
        if (tid < KV_LST) {
            int l = lbeg + ls + tid;
            float s, c;
            sincosf(0.5f * CUDART_PI_F * (float)(l + 1) / (float)LSEQ, &s, &c);
            ssin[tid] = s; scos[tid] = c;
        }
        __syncthreads();
        #pragma unroll
        for (int i = 0; i < 16; i++) {
            int idx = tid + i * 128;          // 0..2047
            int lc = idx >> 5, g = idx & 31;
            int l = lbeg + ls + lc;
            size_t base = ((size_t)(l * BATCH + b)) * EMB + hh * HDIM + g * 2;
            __half2 kh = *(const __half2*)&d_Kh[base];
            __half2 vh = *(const __half2*)&d_Vh[base];
            float2 kf = __half22float2(kh);
            float s = ssin[lc], c = scos[lc];
            *(__half2*)&sk[lc][g * 2]      = __floats2half2_rn(kf.x * s, kf.y * s);
            *(__half2*)&sk[lc][64 + g * 2] = __floats2half2_rn(kf.x * c, kf.y * c);
            *(__half2*)&sv[lc][g * 2]      = vh;
        }
        __syncthreads();
        // ksum over this stage (thread owns dk = tid)
        #pragma unroll 8
        for (int lc = 0; lc < KV_LST; lc++) ksum += __half2float(sk[lc][tid]);

        // MMA: 4 chunks of 16 l
        #pragma unroll
        for (int lc16 = 0; lc16 < 4; lc16++) {
            uint32_t a[2][4], bb[4][4];
            int srA = lc16 * 16 + a_sr;
            #pragma unroll
            for (int t = 0; t < 2; t++)
                ldsm4t(a[t], skb + (uint32_t)srA * 272u + (uint32_t)(wid * 32 + t * 16 + a_sc) * 2u);
            int srB = lc16 * 16 + b_sr;
            #pragma unroll
            for (int g = 0; g < 4; g++)
                ldsm4t(bb[g], svb + (uint32_t)srB * 144u + (uint32_t)(g * 16 + b_sc) * 2u);
            #pragma unroll
            for (int t = 0; t < 2; t++)
                #pragma unroll
                for (int j = 0; j < 8; j++)
                    mma16816(acc[t][j], a[t], bb[j >> 1][2 * (j & 1)], bb[j >> 1][2 * (j & 1) + 1]);
        }
    }

    // write kvT fp32 partial [dv][dk]
    float* kvp = d_kvT + ((size_t)(seg * NHEADS_TOT + n)) * 64 * 128;
    #pragma unroll
    for (int t = 0; t < 2; t++)
        #pragma unroll
        for (int j = 0; j < 8; j++) {
            int m0 = wid * 32 + t * 16 + (lane >> 2);
            int n0 = j * 8 + (lane & 3) * 2;
            kvp[n0 * 128 + m0]             = acc[t][j][0];
            kvp[(n0 + 1) * 128 + m0]       = acc[t][j][1];
            kvp[n0 * 128 + m0 + 8]         = acc[t][j][2];
            kvp[(n0 + 1) * 128 + m0 + 8]   = acc[t][j][3];
        }
    d_ksum[(seg * NHEADS_TOT + n) * 128 + tid] = ksum;
}

// ---------------- attention stage 2: HMMA out + z + residual ---------------
// Block (head n, lb): out[128 l][64 dv] = q_[128l][128dk] @ kvT^T, y = x + z*out
__global__ __launch_bounds__(128) void attn_out_kernel() {
    __shared__ __half skvT[64][136];     // kv^T fp16
    __shared__ __half sq[128][136];      // q_ fp16
    __shared__ float sks[128];
    __shared__ float ssin[128], scos[128], sz[128];
    int n = blockIdx.x, lb = blockIdx.y;
    int b = n / NHEAD, hh = n % NHEAD;
    int tid = threadIdx.x, lane = tid & 31, wid = tid >> 5;
    int l0 = lb * 128;
    uint32_t sqb = smem_to_u32(sq), skvb = smem_to_u32(skvT);

    // 1: reduce kvT partials -> fp16; ksum -> fp32
    {
        const float* kv0 = d_kvT + (size_t)n * 64 * 128;
        #pragma unroll
        for (int i = 0; i < 64; i++) {
            int idx = tid + i * 128;          // 0..8191
            float v = 0.f;
            #pragma unroll
            for (int s = 0; s < NSEG; s++)
                v += kv0[(size_t)s * NHEADS_TOT * 64 * 128 + idx];
            skvT[idx >> 7][idx & 127] = __float2half(v);
        }
        float v = 0.f;
        #pragma unroll
        for (int s = 0; s < NSEG; s++)
            v += d_ksum[(s * NHEADS_TOT + n) * 128 + tid];
        sks[tid] = v;
    }
    {
        int l = l0 + tid;
        float s, c;
        sincosf(0.5f * CUDART_PI_F * (float)(l + 1) / (float)LSEQ, &s, &c);
        ssin[tid] = s; scos[tid] = c;
    }
    __syncthreads();

    // 2: build q_ tile [128 l][128 dk] fp16
    #pragma unroll
    for (int i = 0; i < 32; i++) {
        int idx = tid + i * 128;              // 0..4095
        int lc = idx >> 5, g = idx & 31;
        int m = (l0 + lc) * BATCH + b;
        __half2 qh = *(const __half2*)&d_Qh[(size_t)m * EMB + hh * HDIM + g * 2];
        float2 qf = __half22float2(qh);
        float s = ssin[lc], c = scos[lc];
        *(__half2*)&sq[lc][g * 2]      = __floats2half2_rn(qf.x * s, qf.y * s);
        *(__half2*)&sq[lc][64 + g * 2] = __floats2half2_rn(qf.x * c, qf.y * c);
    }
    __syncthreads();

    // 3: z per l (thread t owns l0+t)
    {
        float dp = 0.f;
        #pragma unroll 16
        for (int d = 0; d < 128; d++)
            dp += __half2float(sq[tid][d]) * sks[d];
        sz[tid] = 1.0f / fmaxf(dp, 1e-6f);
    }
    __syncthreads();

    // 4: MMA out[128l][64dv]: A = sq (non-trans), B = skvT rows [dv][dk]
    float acc[2][8][4];
    #pragma unroll
    for (int t = 0; t < 2; t++)
        #pragma unroll
        for (int j = 0; j < 8; j++)
            #pragma unroll
            for (int i = 0; i < 4; i++) acc[t][j][i] = 0.f;

    int a_mr = lane & 15;
    int a_ks = lane >> 4;
    int b_nr = ((lane >> 4) << 3) | (lane & 7);
    int b_ks = (lane >> 3) & 1;

    #pragma unroll
    for (int kc = 0; kc < 8; kc++) {
        uint32_t ah[2][4], bb[4][4];
        #pragma unroll
        for (int t = 0; t < 2; t++)
            ldsm4(ah[t], sqb + (uint32_t)(wid * 32 + t * 16 + a_mr) * 272u + kc * 32u + a_ks * 16u);
        #pragma unroll
        for (int g = 0; g < 4; g++)
            ldsm4(bb[g], skvb + (uint32_t)(g * 16 + b_nr) * 272u + kc * 32u + b_ks * 16u);
        #pragma unroll
        for (int t = 0; t < 2; t++)
            #pragma unroll
            for (int j = 0; j < 8; j++)
                mma16816(acc[t][j], ah[t], bb[j >> 1][2 * (j & 1)], bb[j >> 1][2 * (j & 1) + 1]);
    }

    // 5: epilogue: y = x + z*out -> tiled fp16 Y
    int g4 = lane >> 2, tq = lane & 3;
    #pragma unroll
    for (int t = 0; t < 2; t++) {
        #pragma unroll
        for (int j = 0; j < 8; j++) {
            int lloc = wid * 32 + t * 16 + g4;
            int dv = j * 8 + tq * 2;
            #pragma unroll
            for (int half = 0; half < 2; half++) {
                int ll = lloc + half * 8;
                float z = sz[ll];
                int m = (l0 + ll) * BATCH + b;
                float2 xv = *(const float2*)&d_X[(size_t)m * EMB + hh * HDIM + dv];
                float y0 = xv.x + z * acc[t][j][half * 2];
                float y1 = xv.y + z * acc[t][j][half * 2 + 1];
                int tile = (m >> 7) * KCH + hh;
                uint32_t ti = tiled_idx(tile, m & 127, dv);
                *(__half2*)&d_Yh[ti] = __floats2half2_rn(y0, y1);
            }
        }
    }
}

// ---------------- launch ----------------
extern "C" void kernel_launch(void* const* d_in, const int* in_sizes, int n_in,
                              void* d_out, int out_size) {
    const float* query = (const float*)d_in[0];
    const float* Wq = (const float*)d_in[1];
    const float* bq = (const float*)d_in[2];
    const float* Wk = (const float*)d_in[3];
    const float* bk = (const float*)d_in[4];
    const float* Wv = (const float*)d_in[5];
    const float* bv = (const float*)d_in[6];
    const float* Wo = (const float*)d_in[7];
    const float* bo = (const float*)d_in[8];
    float* out = (float*)d_out;

    __half *pQh, *pKh, *pVh, *pXh, *pYh, *pWqkv, *pWo;
    cudaGetSymbolAddress((void**)&pQh, d_Qh);
    cudaGetSymbolAddress((void**)&pKh, d_Kh);
    cudaGetSymbolAddress((void**)&pVh, d_Vh);
    cudaGetSymbolAddress((void**)&pXh, d_Xh);
    cudaGetSymbolAddress((void**)&pYh, d_Yh);
    cudaGetSymbolAddress((void**)&pWqkv, d_Wqkv);
    cudaGetSymbolAddress((void**)&pWo, d_Wo);

    cudaFuncSetAttribute(tcgemm_kernel<0>, cudaFuncAttributeMaxDynamicSharedMemorySize, GEMM_SMEM);
    cudaFuncSetAttribute(tcgemm_kernel<1>, cudaFuncAttributeMaxDynamicSharedMemorySize, GEMM_SMEM);

    dim3 tgrid(LSEQ / 32, EMB / 32, BATCH);
    transpose_kernel<<<tgrid, dim3(32, 8)>>>(query);                     // 1
    const int wgrid = (EMB * EMB + 255) / 256;
    wconv3_kernel<<<dim3(wgrid, 3), 256>>>(Wq, Wk, Wv);                  // 2

    // 3: combined QKV GEMM (fp16 single product)
    tcgemm_kernel<0><<<dim3(18, MT), 128, GEMM_SMEM>>>(
        pXh, pWqkv, bq, bk, bv, pQh, pKh, pVh, 0b011);

    // 4 (ncu capture slot): HMMA kv reduction
    attn_kv_kernel<<<dim3(NHEADS_TOT, NSEG), 128>>>();

    // 5: HMMA out + z + residual
    attn_out_kernel<<<dim3(NHEADS_TOT, LSEQ / 128), 128>>>();

    wconvO_kernel<<<wgrid, 256>>>(Wo);                                   // 6

    // 7: O projection (fp16 single product, fp32 out)
    tcgemm_kernel<1><<<dim3(6, MT), 128, GEMM_SMEM>>>(
        pYh, pWo, bo, bo, bo, out, out, out, 0);
}

// round 13
// speedup vs baseline: 2.0037x; 1.0330x over previous
#include <cuda_runtime.h>
#include <cuda_fp16.h>
#include <math_constants.h>
#include <cstdint>

// ---------------- problem constants ----------------
#define BATCH   8
#define EMB     768
#define LSEQ    2304
#define NHEAD   12
#define HDIM    64
#define MROWS   (LSEQ*BATCH)          // 18432
#define NHEADS_TOT (BATCH*NHEAD)      // 96
#define KCH     12                    // K chunks of 64
#define MT      (MROWS/128)           // 144 GEMM M-tiles
#define NSEG    6
#define LSEG    (LSEQ/NSEG)           // 384

// padded tile: 128 rows x 72 fp16 (144B pitch) = 18432 B
#define TILE_PAD    9216
#define TILE_B      18432
#define SMEM_DATA   110592            // 3 stages x 2 tiles
#define GEMM_SMEM   (SMEM_DATA + 128)

typedef unsigned long long u64t;

// ---------------- PTX helpers ----------------
__device__ __forceinline__ uint32_t smem_to_u32(const void* p) {
    uint32_t a;
    asm("{ .reg .u64 t; cvta.to.shared.u64 t, %1; cvt.u32.u64 %0, t; }" : "=r"(a) : "l"(p));
    return a;
}
__device__ __forceinline__ void ldsm4(uint32_t* r, uint32_t addr) {
    asm volatile("ldmatrix.sync.aligned.m8n8.x4.shared.b16 {%0,%1,%2,%3}, [%4];"
        : "=r"(r[0]), "=r"(r[1]), "=r"(r[2]), "=r"(r[3]) : "r"(addr));
}
__device__ __forceinline__ void ldsm4t(uint32_t* r, uint32_t addr) {
    asm volatile("ldmatrix.sync.aligned.m8n8.x4.trans.shared.b16 {%0,%1,%2,%3}, [%4];"
        : "=r"(r[0]), "=r"(r[1]), "=r"(r[2]), "=r"(r[3]) : "r"(addr));
}
__device__ __forceinline__ void mma16816(float* c, const uint32_t* a, uint32_t b0, uint32_t b1) {
    asm volatile("mma.sync.aligned.m16n8k16.row.col.f32.f16.f16.f32 "
        "{%0,%1,%2,%3}, {%4,%5,%6,%7}, {%8,%9}, {%0,%1,%2,%3};"
        : "+f"(c[0]), "+f"(c[1]), "+f"(c[2]), "+f"(c[3])
        : "r"(a[0]), "r"(a[1]), "r"(a[2]), "r"(a[3]), "r"(b0), "r"(b1));
}
#define MBARRIER_INIT(addr, cnt) \
    asm volatile("mbarrier.init.shared.b64 [%0], %1;" :: "r"((uint32_t)(addr)), "r"((uint32_t)(cnt)) : "memory")
#define MBARRIER_ARRIVE(addr) \
    asm volatile("mbarrier.arrive.shared.b64 _, [%0];" :: "r"((uint32_t)(addr)) : "memory")
#define MBARRIER_EXPECT_TX(addr, bytes) \
    asm volatile("mbarrier.arrive.expect_tx.shared.b64 _, [%0], %1;" :: "r"((uint32_t)(addr)), "r"((uint32_t)(bytes)) : "memory")
#define MBARRIER_WAIT_PARITY(mbar_smem_addr, phase_parity) do { \
    uint32_t _mbar = (uint32_t)(mbar_smem_addr); \
    uint32_t _parity = (uint32_t)(phase_parity); \
    uint32_t _done; \
    asm volatile("{\n\t.reg .pred p;\n\t" \
        "mbarrier.try_wait.parity.acquire.cta.shared::cta.b64 p, [%1], %2;\n\t" \
        "selp.b32 %0, 1, 0, p;\n\t}" \
        : "=r"(_done) : "r"(_mbar), "r"(_parity) : "memory"); \
    if (!_done) { \
        asm volatile("{\n\t.reg .pred P1;\n\t" \
            "WAIT_LOOP_%=:\n\t" \
            "mbarrier.try_wait.parity.acquire.cta.shared::cta.b64 P1, [%0], %1, 0x989680;\n\t" \
            "@P1 bra.uni WAIT_DONE_%=;\n\t" \
            "bra.uni WAIT_LOOP_%=;\n\t" \
            "WAIT_DONE_%=:\n\t}" \
            :: "r"(_mbar), "r"(_parity) : "memory"); \
    } \
} while(0)
__device__ __forceinline__ void bulk_g2s(uint32_t dst_smem, const void* gsrc, uint32_t bytes, uint32_t mbar) {
    asm volatile(
        "cp.async.bulk.shared::cluster.global.mbarrier::complete_tx::bytes [%0], [%1], %2, [%3];"
        :: "r"(dst_smem), "l"(gsrc), "r"(bytes), "r"(mbar) : "memory");
}

// ---------------- scratch globals ----------------
__device__ __align__(1024) __half d_Qh[MROWS*EMB];
__device__ __align__(1024) __half d_Kh[MROWS*EMB];
__device__ __align__(1024) __half d_Vh[MROWS*EMB];
__device__ __align__(1024) __half d_Xh[MT*KCH*TILE_PAD];
__device__ __align__(1024) __half d_Yh[MT*KCH*TILE_PAD];
__device__ __align__(1024) __half d_Wqkv[18*KCH*TILE_PAD];
__device__ __align__(1024) __half d_Wo[6*KCH*TILE_PAD];
__device__ float d_kvT[NSEG*NHEADS_TOT*64*128];   // [seg][head][dv][dk] fp32 partials
__device__ float d_ksum[NSEG*NHEADS_TOT*128];
__device__ __align__(16) __half d_kvTh[NHEADS_TOT*64*128];  // reduced fp16 [head][dv][dk]
__device__ float d_ksumR[NHEADS_TOT*128];

__device__ __forceinline__ uint32_t tiled_idx(int tile, int r, int k) {
    return (uint32_t)tile * TILE_PAD + (uint32_t)r * 72u + (uint32_t)k;
}

// ---------------- weight conversion (all 4 weights) ----------------
__global__ void wconv_kernel(const float* __restrict__ Wq, const float* __restrict__ Wk,
                             const float* __restrict__ Wv, const float* __restrict__ Wo) {
    int which = blockIdx.y;
    const float* W = (which == 0) ? Wq : (which == 1) ? Wk : (which == 2) ? Wv : Wo;
    int idx = blockIdx.x * 256 + threadIdx.x;
    if (idx >= EMB * EMB) return;
    int n = idx / EMB, e = idx % EMB;
    __half h = __float2half(W[idx]);
    if (which < 3) {
        uint32_t t = tiled_idx((which * 6 + (n >> 7)) * KCH + (e >> 6), n & 127, e & 63);
        d_Wqkv[t] = h;
    } else {
        uint32_t t = tiled_idx(((n >> 7)) * KCH + (e >> 6), n & 127, e & 63);
        d_Wo[t] = h;
    }
}

// ---------------- transpose (B,E,L)->(L*B,E): fp16 tiled only ---------------
__global__ void transpose_kernel(const float* __restrict__ q) {
    __shared__ float tile[32][33];
    int b  = blockIdx.z;
    int l0 = blockIdx.x * 32;
    int e0 = blockIdx.y * 32;
    int tx = threadIdx.x, ty = threadIdx.y;   // 32 x 8
    const float* src = q + (size_t)b * EMB * LSEQ;
    #pragma unroll
    for (int i = 0; i < 32; i += 8)
        tile[ty + i][tx] = src[(size_t)(e0 + ty + i) * LSEQ + l0 + tx];
    __syncthreads();
    #pragma unroll
    for (int i = 0; i < 32; i += 8) {
        int l = l0 + ty + i;
        int e = e0 + tx;
        int m = l * BATCH + b;
        uint32_t t = tiled_idx((m >> 7) * KCH + (e >> 6), m & 127, e & 63);
        d_Xh[t] = __float2half(tile[tx][ty + i]);
    }
}

// ---------------- HMMA GEMM 128x128 tile, 128 threads, single product -------
// OUT32=0: fp16 output (QKV).  OUT32=1: fp32 output (O-projection).
template <int OUT32>
__global__ __launch_bounds__(128, 2) void tcgemm_kernel(
    const __half* __restrict__ A, const __half* __restrict__ B,
    const float* __restrict__ b0p, const float* __restrict__ b1p, const float* __restrict__ b2p,
    void* __restrict__ C0, void* __restrict__ C1, void* __restrict__ C2,
    int reluMask)
{
    constexpr int NST = 3;
    constexpr uint32_t STAGE_BYTES = 2 * TILE_B;

    extern __shared__ __align__(1024) char smem[];
    uint32_t sb = smem_to_u32(smem);
    int tid  = threadIdx.x;
    int lane = tid & 31, wid = tid >> 5;   // 4 warps
    int nt = blockIdx.x, mt = blockIdx.y;
    int sel = nt / 6, ntc = nt % 6;
    const float* bias = (sel == 0) ? b0p : (sel == 1) ? b1p : b2p;
    void* C = (sel == 0) ? C0 : (sel == 1) ? C1 : C2;
    int doRelu = (reluMask >> sel) & 1;
    int wm = wid & 1;      // M offset wm*64
    int wn = wid >> 1;     // N offset wn*64

    uint32_t mb_full  = sb + SMEM_DATA;
    uint32_t mb_empty = sb + SMEM_DATA + 48;

    if (tid == 0) {
        #pragma unroll
        for (int s = 0; s < NST; s++) {
            MBARRIER_INIT(mb_full + 8 * s, 1);
            MBARRIER_INIT(mb_empty + 8 * s, 128);
        }
        asm volatile("fence.proxy.async.shared::cta;" ::: "memory");
    }
    __syncthreads();

    const __half* gA = A + (size_t)mt * KCH * TILE_PAD;
    const __half* gB = B + (size_t)nt * KCH * TILE_PAD;

    int emptyPh[NST], fullPh[NST];
    #pragma unroll
    for (int s = 0; s < NST; s++) { emptyPh[s] = 1; fullPh[s] = 0; }

    auto produce = [&](int c) {
        if (tid == 0) {
            int s = c % NST;
            MBARRIER_WAIT_PARITY(mb_empty + 8 * s, emptyPh[s]);
            emptyPh[s] ^= 1;
            uint32_t dst = sb + s * STAGE_BYTES;
            uint32_t mbar = mb_full + 8 * s;
            MBARRIER_EXPECT_TX(mbar, STAGE_BYTES);
            bulk_g2s(dst,          gA + (size_t)c * TILE_PAD, TILE_B, mbar);
            bulk_g2s(dst + TILE_B, gB + (size_t)c * TILE_PAD, TILE_B, mbar);
        }
    };

    float acc[4][8][4];
    #pragma unroll
    for (int t = 0; t < 4; t++)
        #pragma unroll
        for (int j = 0; j < 8; j++)
            #pragma unroll
            for (int i = 0; i < 4; i++) acc[t][j][i] = 0.f;

    int a_mr = lane & 15;
    int a_ks = lane >> 4;
    int b_nr = ((lane >> 4) << 3) | (lane & 7);
    int b_ks = (lane >> 3) & 1;

    #pragma unroll
    for (int s = 0; s < NST; s++) produce(s);

    for (int c = 0; c < KCH; c++) {
        int s = c % NST;
        MBARRIER_WAIT_PARITY(mb_full + 8 * s, fullPh[s]);
        fullPh[s] ^= 1;

        uint32_t stB = sb + s * STAGE_BYTES;
        uint32_t aRow0 = (uint32_t)(wm * 64);

        #pragma unroll
        for (int ks = 0; ks < 4; ks++) {
            uint32_t ah[4][4], bb[4][4];
            #pragma unroll
            for (int t = 0; t < 4; t++) {
                uint32_t off = (aRow0 + t * 16 + a_mr) * 144u + ks * 32u + a_ks * 16u;
                ldsm4(ah[t], stB + off);
            }
            #pragma unroll
            for (int g = 0; g < 4; g++) {
                uint32_t off = (uint32_t)(wn * 64 + g * 16 + b_nr) * 144u + ks * 32u + b_ks * 16u;
                ldsm4(bb[g], stB + TILE_B + off);
            }
            #pragma unroll
            for (int t = 0; t < 4; t++)
                #pragma unroll
                for (int j = 0; j < 8; j++)
                    mma16816(acc[t][j], ah[t], bb[j >> 1][2 * (j & 1)], bb[j >> 1][2 * (j & 1) + 1]);
        }
        MBARRIER_ARRIVE(mb_empty + 8 * s);
        if (c + NST < KCH) produce(c + NST);
    }

    // epilogue
    int g = lane >> 2, tq = lane & 3;
    int mbase = mt * 128 + wm * 64;
    #pragma unroll
    for (int t = 0; t < 4; t++) {
        int r0 = mbase + t * 16 + g;
        #pragma unroll
        for (int j = 0; j < 8; j++) {
            int col = ntc * 128 + wn * 64 + j * 8 + tq * 2;
            float b0 = __ldg(&bias[col]), b1 = __ldg(&bias[col + 1]);
            float v0 = acc[t][j][0] + b0, v1 = acc[t][j][1] + b1;
            float v2 = acc[t][j][2] + b0, v3 = acc[t][j][3] + b1;
            if (doRelu) {
                v0 = fmaxf(v0, 0.f); v1 = fmaxf(v1, 0.f);
                v2 = fmaxf(v2, 0.f); v3 = fmaxf(v3, 0.f);
            }
            if (!OUT32) {
                __half* Ch = (__half*)C;
                *(__half2*)&Ch[(size_t)r0 * EMB + col]       = __floats2half2_rn(v0, v1);
                *(__half2*)&Ch[(size_t)(r0 + 8) * EMB + col] = __floats2half2_rn(v2, v3);
            } else {
                float* Cf = (float*)C;
                *(float2*)&Cf[(size_t)r0 * EMB + col]       = make_float2(v0, v1);
                *(float2*)&Cf[(size_t)(r0 + 8) * EMB + col] = make_float2(v2, v3);
            }
        }
    }
}

// ---------------- attention stage 1: HMMA kv reduction ----------------------
#define KV_LST 64
__global__ __launch_bounds__(128) void attn_kv_kernel() {
    __shared__ __half sk[KV_LST][136];   // k_ = [k*sin | k*cos]
    __shared__ __half sv[KV_LST][72];    // v
    __shared__ float ssin[KV_LST], scos[KV_LST];
    int n = blockIdx.x, seg = blockIdx.y;
    int b = n / NHEAD, hh = n % NHEAD;
    int tid = threadIdx.x, lane = tid & 31, wid = tid >> 5;
    uint32_t skb = smem_to_u32(sk), svb = smem_to_u32(sv);

    float acc[2][8][4];
    #pragma unroll
    for (int t = 0; t < 2; t++)
        #pragma unroll
        for (int j = 0; j < 8; j++)
            #pragma unroll
            for (int i = 0; i < 4; i++) acc[t][j][i] = 0.f;
    float ksum = 0.f;

    int a_sr = (lane & 7) + ((lane >> 4) << 3);
    int a_sc = ((lane >> 3) & 1) * 8;
    int b_sr = (lane & 7) + (((lane >> 3) & 1) << 3);
    int b_sc = (lane >> 4) * 8;

    int lbeg = seg * LSEG;
    for (int ls = 0; ls < LSEG; ls += KV_LST) {
        __syncthreads();
        if (tid < KV_LST) {
            int l = lbeg + ls + tid;
            float s, c;
            sincosf(0.5f * CUDART_PI_F * (float)(l + 1) / (float)LSEQ, &s, &c);
            ssin[tid] = s; scos[tid] = c;
        }
        __syncthreads();
        #pragma unroll
        for (int i = 0; i < 16; i++) {
            int idx = tid + i * 128;
            int lc = idx >> 5, g = idx & 31;
            int l = lbeg + ls + lc;
            size_t base = ((size_t)(l * BATCH + b)) * EMB + hh * HDIM + g * 2;
            __half2 kh = *(const __half2*)&d_Kh[base];
            __half2 vh = *(const __half2*)&d_Vh[base];
            float2 kf = __half22float2(kh);
            float s = ssin[lc], c = scos[lc];
            *(__half2*)&sk[lc][g * 2]      = __floats2half2_rn(kf.x * s, kf.y * s);
            *(__half2*)&sk[lc][64 + g * 2] = __floats2half2_rn(kf.x * c, kf.y * c);
            *(__half2*)&sv[lc][g * 2]      = vh;
        }
        __syncthreads();
        #pragma unroll 8
        for (int lc = 0; lc < KV_LST; lc++) ksum += __half2float(sk[lc][tid]);

        #pragma unroll
        for (int lc16 = 0; lc16 < 4; lc16++) {
            uint32_t a[2][4], bb[4][4];
            int srA = lc16 * 16 + a_sr;
            #pragma unroll
            for (int t = 0; t < 2; t++)
                ldsm4t(a[t], skb + (uint32_t)srA * 272u + (uint32_t)(wid * 32 + t * 16 + a_sc) * 2u);
            int srB = lc16 * 16 + b_sr;
            #pragma unroll
            for (int g = 0; g < 4; g++)
                ldsm4t(bb[g], svb + (uint32_t)srB * 144u + (uint32_t)(g * 16 + b_sc) * 2u);
            #pragma unroll
            for (int t = 0; t < 2; t++)
                #pragma unroll
                for (int j = 0; j < 8; j++)
                    mma16816(acc[t][j], a[t], bb[j >> 1][2 * (j & 1)], bb[j >> 1][2 * (j & 1) + 1]);
        }
    }

    float* kvp = d_kvT + ((size_t)(seg * NHEADS_TOT + n)) * 64 * 128;
    #pragma unroll
    for (int t = 0; t < 2; t++)
        #pragma unroll
        for (int j = 0; j < 8; j++) {
            int m0 = wid * 32 + t * 16 + (lane >> 2);
            int n0 = j * 8 + (lane & 3) * 2;
            kvp[n0 * 128 + m0]             = acc[t][j][0];
            kvp[(n0 + 1) * 128 + m0]       = acc[t][j][1];
            kvp[n0 * 128 + m0 + 8]         = acc[t][j][2];
            kvp[(n0 + 1) * 128 + m0 + 8]   = acc[t][j][3];
        }
    d_ksum[(seg * NHEADS_TOT + n) * 128 + tid] = ksum;
}

// ---------------- kv partial reduction: fp32 x NSEG -> fp16 -----------------
__global__ __launch_bounds__(256) void kvreduce_kernel() {
    int n = blockIdx.x;
    int tid = threadIdx.x;
    const float* kv0 = d_kvT + (size_t)n * 8192;
    #pragma unroll
    for (int i = 0; i < 32; i++) {
        int idx = tid + i * 256;
        float v = 0.f;
        #pragma unroll
        for (int s = 0; s < NSEG; s++)
            v += kv0[(size_t)s * NHEADS_TOT * 8192 + idx];
        d_kvTh[(size_t)n * 8192 + idx] = __float2half(v);
    }
    if (tid < 128) {
        float v = 0.f;
        #pragma unroll
        for (int s = 0; s < NSEG; s++)
            v += d_ksum[(s * NHEADS_TOT + n) * 128 + tid];
        d_ksumR[n * 128 + tid] = v;
    }
}

// ---------------- attention stage 2: HMMA out + z + residual ---------------
__global__ __launch_bounds__(128) void attn_out_kernel() {
    __shared__ __half skvT[64][136];
    __shared__ __half sq[128][136];
    __shared__ float sks[128];
    __shared__ float ssin[128], scos[128], sz[128];
    int n = blockIdx.x, lb = blockIdx.y;
    int b = n / NHEAD, hh = n % NHEAD;
    int tid = threadIdx.x, lane = tid & 31, wid = tid >> 5;
    int l0 = lb * 128;
    uint32_t sqb = smem_to_u32(sq), skvb = smem_to_u32(skvT);

    // 1: load reduced kv (fp16, 16KB) + ksum
    {
        const uint4* kvh = (const uint4*)(d_kvTh + (size_t)n * 8192);
        #pragma unroll
        for (int i = 0; i < 8; i++) {
            int idx4 = tid + i * 128;          // 0..1023, each = 8 halfs
            int row = idx4 >> 4, col = (idx4 & 15) * 8;
            *(uint4*)&skvT[row][col] = kvh[idx4];
        }
        sks[tid] = d_ksumR[n * 128 + tid];
    }
    {
        int l = l0 + tid;
        float s, c;
        sincosf(0.5f * CUDART_PI_F * (float)(l + 1) / (float)LSEQ, &s, &c);
        ssin[tid] = s; scos[tid] = c;
    }
    __syncthreads();

    // 2: build q_ tile [128 l][128 dk] fp16
    #pragma unroll
    for (int i = 0; i < 32; i++) {
        int idx = tid + i * 128;
        int lc = idx >> 5, g = idx & 31;
        int m = (l0 + lc) * BATCH + b;
        __half2 qh = *(const __half2*)&d_Qh[(size_t)m * EMB + hh * HDIM + g * 2];
        float2 qf = __half22float2(qh);
        float s = ssin[lc], c = scos[lc];
        *(__half2*)&sq[lc][g * 2]      = __floats2half2_rn(qf.x * s, qf.y * s);
        *(__half2*)&sq[lc][64 + g * 2] = __floats2half2_rn(qf.x * c, qf.y * c);
    }
    __syncthreads();

    // 3: z per l
    {
        float dp = 0.f;
        #pragma unroll 16
        for (int d = 0; d < 128; d++)
            dp += __half2float(sq[tid][d]) * sks[d];
        sz[tid] = 1.0f / fmaxf(dp, 1e-6f);
    }
    __syncthreads();

    // 4: MMA out[128l][64dv]
    float acc[2][8][4];
    #pragma unroll
    for (int t = 0; t < 2; t++)
        #pragma unroll
        for (int j = 0; j < 8; j++)
            #pragma unroll
            for (int i = 0; i < 4; i++) acc[t][j][i] = 0.f;

    int a_mr = lane & 15;
    int a_ks = lane >> 4;
    int b_nr = ((lane >> 4) << 3) | (lane & 7);
    int b_ks = (lane >> 3) & 1;

    #pragma unroll
    for (int kc = 0; kc < 8; kc++) {
        uint32_t ah[2][4], bb[4][4];
        #pragma unroll
        for (int t = 0; t < 2; t++)
            ldsm4(ah[t], sqb + (uint32_t)(wid * 32 + t * 16 + a_mr) * 272u + kc * 32u + a_ks * 16u);
        #pragma unroll
        for (int g = 0; g < 4; g++)
            ldsm4(bb[g], skvb + (uint32_t)(g * 16 + b_nr) * 272u + kc * 32u + b_ks * 16u);
        #pragma unroll
        for (int t = 0; t < 2; t++)
            #pragma unroll
            for (int j = 0; j < 8; j++)
                mma16816(acc[t][j], ah[t], bb[j >> 1][2 * (j & 1)], bb[j >> 1][2 * (j & 1) + 1]);
    }

    // 5: epilogue: y = x + z*out (x from fp16 tiled Xh) -> tiled fp16 Y
    int g4 = lane >> 2, tq = lane & 3;
    #pragma unroll
    for (int t = 0; t < 2; t++) {
        #pragma unroll
        for (int j = 0; j < 8; j++) {
            int lloc = wid * 32 + t * 16 + g4;
            int dv = j * 8 + tq * 2;
            #pragma unroll
            for (int half = 0; half < 2; half++) {
                int ll = lloc + half * 8;
                float z = sz[ll];
                int m = (l0 + ll) * BATCH + b;
                int tile = (m >> 7) * KCH + hh;
                uint32_t ti = tiled_idx(tile, m & 127, dv);
                float2 xv = __half22float2(*(const __half2*)&d_Xh[ti]);
                float y0 = xv.x + z * acc[t][j][half * 2];
                float y1 = xv.y + z * acc[t][j][half * 2 + 1];
                *(__half2*)&d_Yh[ti] = __floats2half2_rn(y0, y1);
            }
        }
    }
}

// ---------------- launch ----------------
extern "C" void kernel_launch(void* const* d_in, const int* in_sizes, int n_in,
                              void* d_out, int out_size) {
    const float* query = (const float*)d_in[0];
    const float* Wq = (const float*)d_in[1];
    const float* bq = (const float*)d_in[2];
    const float* Wk = (const float*)d_in[3];
    const float* bk = (const float*)d_in[4];
    const float* Wv = (const float*)d_in[5];
    const float* bv = (const float*)d_in[6];
    const float* Wo = (const float*)d_in[7];
    const float* bo = (const float*)d_in[8];
    float* out = (float*)d_out;

    __half *pQh, *pKh, *pVh, *pXh, *pYh, *pWqkv, *pWo;
    cudaGetSymbolAddress((void**)&pQh, d_Qh);
    cudaGetSymbolAddress((void**)&pKh, d_Kh);
    cudaGetSymbolAddress((void**)&pVh, d_Vh);
    cudaGetSymbolAddress((void**)&pXh, d_Xh);
    cudaGetSymbolAddress((void**)&pYh, d_Yh);
    cudaGetSymbolAddress((void**)&pWqkv, d_Wqkv);
    cudaGetSymbolAddress((void**)&pWo, d_Wo);

    cudaFuncSetAttribute(tcgemm_kernel<0>, cudaFuncAttributeMaxDynamicSharedMemorySize, GEMM_SMEM);
    cudaFuncSetAttribute(tcgemm_kernel<1>, cudaFuncAttributeMaxDynamicSharedMemorySize, GEMM_SMEM);

    dim3 tgrid(LSEQ / 32, EMB / 32, BATCH);
    transpose_kernel<<<tgrid, dim3(32, 8)>>>(query);                     // 1
    const int wgrid = (EMB * EMB + 255) / 256;
    wconv_kernel<<<dim3(wgrid, 4), 256>>>(Wq, Wk, Wv, Wo);               // 2

    // 3: combined QKV GEMM (fp16 single product)
    tcgemm_kernel<0><<<dim3(18, MT), 128, GEMM_SMEM>>>(
        pXh, pWqkv, bq, bk, bv, pQh, pKh, pVh, 0b011);

    // 4 (ncu capture slot): HMMA kv reduction
    attn_kv_kernel<<<dim3(NHEADS_TOT, NSEG), 128>>>();

    kvreduce_kernel<<<NHEADS_TOT, 256>>>();                              // 5

    // 6: HMMA out + z + residual
    attn_out_kernel<<<dim3(NHEADS_TOT, LSEQ / 128), 128>>>();

    // 7: O projection (fp16 single product, fp32 out)
    tcgemm_kernel<1><<<dim3(6, MT), 128, GEMM_SMEM>>>(
        pYh, pWo, bo, bo, bo, out, out, out, 0);
}